// round 1
// baseline (speedup 1.0000x reference)
#include <cuda_runtime.h>
#include <math.h>

// Problem constants
#define BB 8
#define NN 2048
#define FF 512
#define HH 256
#define LL 3
#define LN_EPS 1e-5f

// ---------------------------------------------------------------------------
// Device scratch (static allocation — harness forbids cudaMalloc)
// ---------------------------------------------------------------------------
__device__ float g_norm_adj[(size_t)BB * NN * NN];   // 134 MB
__device__ float g_h[(size_t)BB * NN * HH];          // 16.8 MB
__device__ float g_agg[(size_t)BB * NN * HH];        // 16.8 MB
__device__ float g_tmp[(size_t)BB * NN * HH];        // 16.8 MB

// ---------------------------------------------------------------------------
// Kernel 1: build normalized adjacency
// norm_adj[b,r,c] = w / (rowsum(w) + 1e-8),  w = min(adj + I, 1) * edge
// One block per (b, row). 256 threads, row cached in smem.
// ---------------------------------------------------------------------------
__global__ __launch_bounds__(256) void norm_adj_kernel(
    const float* __restrict__ adj, const float* __restrict__ ew,
    float* __restrict__ out)
{
    const int row = blockIdx.x;
    const int b   = blockIdx.y;
    const size_t base = ((size_t)b * NN + row) * NN;
    const float* __restrict__ arow = adj + base;
    const float* __restrict__ erow = ew + base;
    float* __restrict__ orow = out + base;

    __shared__ float w[NN];            // 8 KB
    __shared__ float sbuf[8];

    float lsum = 0.f;
#pragma unroll
    for (int i = 0; i < NN / 256; i++) {
        int c = threadIdx.x + i * 256;
        float a = arow[c] + (c == row ? 1.0f : 0.0f);
        a = fminf(a, 1.0f);
        float v = a * erow[c];
        w[c] = v;
        lsum += v;
    }
    // block reduce lsum
#pragma unroll
    for (int o = 16; o > 0; o >>= 1) lsum += __shfl_down_sync(0xffffffffu, lsum, o);
    int lane = threadIdx.x & 31, wid = threadIdx.x >> 5;
    if (lane == 0) sbuf[wid] = lsum;
    __syncthreads();
    if (wid == 0) {
        float v = (lane < 8) ? sbuf[lane] : 0.f;
#pragma unroll
        for (int o = 4; o > 0; o >>= 1) v += __shfl_down_sync(0xffffffffu, v, o);
        if (lane == 0) sbuf[0] = v;
    }
    __syncthreads();
    const float inv = 1.0f / (sbuf[0] + 1e-8f);

#pragma unroll
    for (int i = 0; i < NN / 256; i++) {
        int c = threadIdx.x + i * 256;
        orow[c] = w[c] * inv;
    }
}

// ---------------------------------------------------------------------------
// Kernel 2: classic register-blocked SGEMM, C = A @ B (row-major).
// BM=BN=128, BK=8, 256 threads, 8x8 accumulators per thread.
// Batched via blockIdx.z with element strides. Requires M%128==0, N%128==0,
// K%8==0 (all shapes here satisfy this).
// ---------------------------------------------------------------------------
__global__ __launch_bounds__(256) void sgemm128(
    const float* __restrict__ A, const float* __restrict__ B,
    float* __restrict__ C,
    int M, int N, int K,
    long strideA, long strideB, long strideC)
{
    const int bz = blockIdx.z;
    A += (long)bz * strideA;
    B += (long)bz * strideB;
    C += (long)bz * strideC;

    const int block_m = blockIdx.y * 128;
    const int block_n = blockIdx.x * 128;

    __shared__ float As[8][128];
    __shared__ float Bs[8][128];

    const int tid = threadIdx.x;
    // A tile load mapping: 128 rows x 8 cols, one float4 per thread
    const int a_row = tid >> 1;           // 0..127
    const int a_col = (tid & 1) * 4;      // 0 or 4
    // B tile load mapping: 8 rows x 128 cols, one float4 per thread
    const int b_row = tid >> 5;           // 0..7
    const int b_col = (tid & 31) * 4;     // 0..124

    const int tx = tid & 15;              // 0..15
    const int ty = tid >> 4;              // 0..15

    const float* Aptr = A + (long)(block_m + a_row) * K + a_col;
    const float* Bptr = B + (long)b_row * N + block_n + b_col;

    float acc[8][8];
#pragma unroll
    for (int i = 0; i < 8; i++)
#pragma unroll
        for (int j = 0; j < 8; j++) acc[i][j] = 0.f;

    for (int k0 = 0; k0 < K; k0 += 8) {
        float4 av = *(const float4*)(Aptr + k0);
        As[a_col + 0][a_row] = av.x;
        As[a_col + 1][a_row] = av.y;
        As[a_col + 2][a_row] = av.z;
        As[a_col + 3][a_row] = av.w;
        *(float4*)&Bs[b_row][b_col] = *(const float4*)(Bptr + (long)k0 * N);
        __syncthreads();

#pragma unroll
        for (int k = 0; k < 8; k++) {
            float a[8], bb[8];
            float4 a0 = *(const float4*)&As[k][ty * 4];
            float4 a1 = *(const float4*)&As[k][64 + ty * 4];
            float4 b0 = *(const float4*)&Bs[k][tx * 4];
            float4 b1 = *(const float4*)&Bs[k][64 + tx * 4];
            a[0] = a0.x; a[1] = a0.y; a[2] = a0.z; a[3] = a0.w;
            a[4] = a1.x; a[5] = a1.y; a[6] = a1.z; a[7] = a1.w;
            bb[0] = b0.x; bb[1] = b0.y; bb[2] = b0.z; bb[3] = b0.w;
            bb[4] = b1.x; bb[5] = b1.y; bb[6] = b1.z; bb[7] = b1.w;
#pragma unroll
            for (int i = 0; i < 8; i++)
#pragma unroll
                for (int j = 0; j < 8; j++)
                    acc[i][j] = fmaf(a[i], bb[j], acc[i][j]);
        }
        __syncthreads();
    }

#pragma unroll
    for (int i = 0; i < 8; i++) {
        int row = block_m + ((i < 4) ? (ty * 4 + i) : (64 + ty * 4 + (i - 4)));
#pragma unroll
        for (int jh = 0; jh < 2; jh++) {
            float4 v;
            v.x = acc[i][jh * 4 + 0];
            v.y = acc[i][jh * 4 + 1];
            v.z = acc[i][jh * 4 + 2];
            v.w = acc[i][jh * 4 + 3];
            int col = block_n + jh * 64 + tx * 4;
            *(float4*)(C + (long)row * N + col) = v;
        }
    }
}

// ---------------------------------------------------------------------------
// Kernel 3: fused bias + LayerNorm + ReLU (+ optional residual).
// One 256-thread block per row (H == 256, one element per thread).
// out[row,j] = relu( LN(Z[row]+bias) * gamma + beta )[j]  (+ residual[row,j])
// ---------------------------------------------------------------------------
__global__ __launch_bounds__(256) void ln_act_kernel(
    const float* __restrict__ Z, const float* __restrict__ bias,
    const float* __restrict__ gamma, const float* __restrict__ beta,
    const float* __restrict__ residual, float* __restrict__ out)
{
    const long row = blockIdx.x;
    const int j = threadIdx.x;
    const long idx = row * HH + j;

    float z = Z[idx] + bias[j];

    // combined (sum, sumsq) block reduction
    float s = z, q = z * z;
#pragma unroll
    for (int o = 16; o > 0; o >>= 1) {
        s += __shfl_down_sync(0xffffffffu, s, o);
        q += __shfl_down_sync(0xffffffffu, q, o);
    }
    __shared__ float2 sbuf[8];
    int lane = threadIdx.x & 31, wid = threadIdx.x >> 5;
    if (lane == 0) sbuf[wid] = make_float2(s, q);
    __syncthreads();
    if (wid == 0) {
        float2 p = (lane < 8) ? sbuf[lane] : make_float2(0.f, 0.f);
#pragma unroll
        for (int o = 4; o > 0; o >>= 1) {
            p.x += __shfl_down_sync(0xffffffffu, p.x, o);
            p.y += __shfl_down_sync(0xffffffffu, p.y, o);
        }
        if (lane == 0) sbuf[0] = p;
    }
    __syncthreads();
    const float mu  = sbuf[0].x * (1.0f / HH);
    const float var = sbuf[0].y * (1.0f / HH) - mu * mu;
    const float rstd = rsqrtf(var + LN_EPS);

    float y = (z - mu) * rstd * gamma[j] + beta[j];
    y = fmaxf(y, 0.0f);
    if (residual) y += residual[idx];
    out[idx] = y;
}

// ---------------------------------------------------------------------------
// Launch orchestration (graph-capturable: kernel launches only)
// ---------------------------------------------------------------------------
extern "C" void kernel_launch(void* const* d_in, const int* in_sizes, int n_in,
                              void* d_out, int out_size)
{
    const float* node_feat = (const float*)d_in[0];   // [B,N,F]
    const float* edge_w    = (const float*)d_in[1];   // [B,N,N]
    const float* adj       = (const float*)d_in[2];   // [B,N,N]
    const float* W_in      = (const float*)d_in[3];   // [F,H]
    const float* b_in      = (const float*)d_in[4];   // [H]
    const float* g_in      = (const float*)d_in[5];   // [H]
    const float* bt_in     = (const float*)d_in[6];   // [H]
    const float* W         = (const float*)d_in[7];   // [L,H,H]
    const float* bvec      = (const float*)d_in[8];   // [L,H]
    const float* gamma     = (const float*)d_in[9];   // [L,H]
    const float* beta      = (const float*)d_in[10];  // [L,H]
    float* out = (float*)d_out;                       // [B,N,H]

    float *na_p, *h_p, *agg_p, *tmp_p;
    cudaGetSymbolAddress((void**)&na_p,  g_norm_adj);
    cudaGetSymbolAddress((void**)&h_p,   g_h);
    cudaGetSymbolAddress((void**)&agg_p, g_agg);
    cudaGetSymbolAddress((void**)&tmp_p, g_tmp);

    const int M_all = BB * NN;  // 16384

    // 1. normalized adjacency
    norm_adj_kernel<<<dim3(NN, BB), 256>>>(adj, edge_w, na_p);

    // 2. input projection: tmp = node_feat @ W_in   [16384,512]@[512,256]
    sgemm128<<<dim3(HH / 128, M_all / 128, 1), 256>>>(
        node_feat, W_in, tmp_p, M_all, HH, FF, 0, 0, 0);

    // 3. h = relu(LN(tmp + b_in))
    ln_act_kernel<<<M_all, 256>>>(tmp_p, b_in, g_in, bt_in, nullptr, h_p);

    // 4. GNN layers
    for (int l = 0; l < LL; l++) {
        // agg[b] = norm_adj[b] @ h[b]   [2048,2048]@[2048,256], batched
        sgemm128<<<dim3(HH / 128, NN / 128, BB), 256>>>(
            na_p, h_p, agg_p, NN, HH, NN,
            (long)NN * NN, (long)NN * HH, (long)NN * HH);

        // tmp = agg @ W[l]   [16384,256]@[256,256]
        sgemm128<<<dim3(HH / 128, M_all / 128, 1), 256>>>(
            agg_p, W + (long)l * HH * HH, tmp_p, M_all, HH, HH, 0, 0, 0);

        // h = relu(LN(tmp + b[l])) + h   (last layer writes to d_out)
        float* dst = (l == LL - 1) ? out : h_p;
        ln_act_kernel<<<M_all, 256>>>(
            tmp_p, bvec + (long)l * HH, gamma + (long)l * HH,
            beta + (long)l * HH, h_p, dst);
    }
}

// round 4
// speedup vs baseline: 3.3093x; 3.3093x over previous
#include <cuda_runtime.h>
#include <math.h>
#include <stdint.h>

// Problem constants
#define BB 8
#define NN 2048
#define FF 512
#define HH 256
#define LL 3
#define LN_EPS 1e-5f

// ---------------------------------------------------------------------------
// Device scratch (static — no cudaMalloc allowed)
// ---------------------------------------------------------------------------
__device__ __align__(128) float g_norm_adj[(size_t)BB * NN * NN];  // 134 MB (tf32-rounded)
__device__ __align__(128) float g_nf[(size_t)BB * NN * FF];        // 33.5 MB (tf32-rounded node_feat)
__device__ __align__(128) float g_h[(size_t)BB * NN * HH];         // fp32
__device__ __align__(128) float g_hT[(size_t)BB * HH * NN];        // tf32-rounded
__device__ __align__(128) float g_agg[(size_t)BB * NN * HH];       // tf32-rounded (GEMM1 out)
__device__ __align__(128) float g_tmp[(size_t)BB * NN * HH];       // fp32
__device__ __align__(128) float g_wT[256 * 512 + 3 * 256 * 256];   // tf32-rounded W_in^T, W[l]^T

// ---------------------------------------------------------------------------
// Helpers
// ---------------------------------------------------------------------------
__device__ __forceinline__ float tf32r(float x) {
    uint32_t u;
    asm("cvt.rna.tf32.f32 %0, %1;" : "=r"(u) : "f"(x));
    return __uint_as_float(u);
}

__device__ __forceinline__ uint32_t smem_u32(const void* p) {
    uint32_t a;
    asm("{ .reg .u64 t; cvta.to.shared.u64 t, %1; cvt.u32.u64 %0, t; }" : "=r"(a) : "l"(p));
    return a;
}

__device__ __forceinline__ void cp16(uint32_t dst, const void* src) {
    asm volatile("cp.async.cg.shared.global [%0], [%1], 16;" :: "r"(dst), "l"(src) : "memory");
}
__device__ __forceinline__ void cp_commit() {
    asm volatile("cp.async.commit_group;" ::: "memory");
}
template <int N> __device__ __forceinline__ void cp_wait() {
    asm volatile("cp.async.wait_group %0;" :: "n"(N) : "memory");
}

__device__ __forceinline__ void ldsm_x4(uint32_t* r, uint32_t addr) {
    asm volatile("ldmatrix.sync.aligned.m8n8.x4.shared.b16 {%0,%1,%2,%3}, [%4];"
                 : "=r"(r[0]), "=r"(r[1]), "=r"(r[2]), "=r"(r[3]) : "r"(addr));
}
__device__ __forceinline__ void ldsm_x2(uint32_t* r, uint32_t addr) {
    asm volatile("ldmatrix.sync.aligned.m8n8.x2.shared.b16 {%0,%1}, [%2];"
                 : "=r"(r[0]), "=r"(r[1]) : "r"(addr));
}

__device__ __forceinline__ void mma_tf32(float* c, const uint32_t* a, const uint32_t* b) {
    asm volatile("mma.sync.aligned.m16n8k8.row.col.f32.tf32.tf32.f32 "
                 "{%0,%1,%2,%3}, {%4,%5,%6,%7}, {%8,%9}, {%0,%1,%2,%3};"
                 : "+f"(c[0]), "+f"(c[1]), "+f"(c[2]), "+f"(c[3])
                 : "r"(a[0]), "r"(a[1]), "r"(a[2]), "r"(a[3]), "r"(b[0]), "r"(b[1]));
}

// ---------------------------------------------------------------------------
// Kernel 1: normalized adjacency (tf32-rounded output; it is GEMM1's A operand)
// ---------------------------------------------------------------------------
__global__ __launch_bounds__(256) void norm_adj_kernel(
    const float* __restrict__ adj, const float* __restrict__ ew,
    float* __restrict__ out)
{
    const int row = blockIdx.x;
    const int b   = blockIdx.y;
    const size_t base = ((size_t)b * NN + row) * NN;
    const float* __restrict__ arow = adj + base;
    const float* __restrict__ erow = ew + base;
    float* __restrict__ orow = out + base;

    __shared__ float w[NN];
    __shared__ float sbuf[8];

    float lsum = 0.f;
#pragma unroll
    for (int i = 0; i < NN / 256; i++) {
        int c = threadIdx.x + i * 256;
        float a = arow[c] + (c == row ? 1.0f : 0.0f);
        a = fminf(a, 1.0f);
        float v = a * erow[c];
        w[c] = v;
        lsum += v;
    }
#pragma unroll
    for (int o = 16; o > 0; o >>= 1) lsum += __shfl_down_sync(0xffffffffu, lsum, o);
    int lane = threadIdx.x & 31, wid = threadIdx.x >> 5;
    if (lane == 0) sbuf[wid] = lsum;
    __syncthreads();
    if (wid == 0) {
        float v = (lane < 8) ? sbuf[lane] : 0.f;
#pragma unroll
        for (int o = 4; o > 0; o >>= 1) v += __shfl_down_sync(0xffffffffu, v, o);
        if (lane == 0) sbuf[0] = v;
    }
    __syncthreads();
    const float inv = 1.0f / (sbuf[0] + 1e-8f);

#pragma unroll
    for (int i = 0; i < NN / 256; i++) {
        int c = threadIdx.x + i * 256;
        orow[c] = tf32r(w[c] * inv);
    }
}

// ---------------------------------------------------------------------------
// Kernel 2: batched 32x32 transpose with tf32 rounding (outputs are B operands)
// ---------------------------------------------------------------------------
__global__ __launch_bounds__(256) void transpose_kernel(
    const float* __restrict__ in, float* __restrict__ out,
    int R, int C, long sIn, long sOut)
{
    __shared__ float tile[32][33];
    const int bz = blockIdx.z;
    in  += (long)bz * sIn;
    out += (long)bz * sOut;
    const int c0 = blockIdx.x * 32;
    const int r0 = blockIdx.y * 32;
    const int tx = threadIdx.x, ty = threadIdx.y;
#pragma unroll
    for (int i = 0; i < 4; i++)
        tile[ty + i * 8][tx] = in[(long)(r0 + ty + i * 8) * C + c0 + tx];
    __syncthreads();
#pragma unroll
    for (int i = 0; i < 4; i++)
        out[(long)(c0 + ty + i * 8) * R + r0 + tx] = tf32r(tile[tx][ty + i * 8]);
}

// ---------------------------------------------------------------------------
// Kernel 2b: elementwise tf32 rounding copy (node_feat -> g_nf)
// ---------------------------------------------------------------------------
__global__ __launch_bounds__(256) void round_copy_kernel(
    const float4* __restrict__ in, float4* __restrict__ out)
{
    long i = (long)blockIdx.x * 256 + threadIdx.x;
    float4 v = in[i];
    v.x = tf32r(v.x); v.y = tf32r(v.y); v.z = tf32r(v.z); v.w = tf32r(v.w);
    out[i] = v;
}

// ---------------------------------------------------------------------------
// Kernel 3: TF32 tensor-core GEMM via mma.sync (baseline-PTX, no tcgen05).
// C[bm:bm+128, bn:bn+128] = A[M,K] @ Bt[N,K]^T   (ldc = 256)
// 256 threads = 8 warps (2m x 4n), warp tile 64x32, Kc=32 double-buffered,
// cp.async staging with xor swizzle, ldmatrix fragment loads.
// grid: (N/128, M/128, batch). K % 32 == 0. Inputs must be tf32-pre-rounded.
// ---------------------------------------------------------------------------
#define KC 32
__global__ __launch_bounds__(256, 2) void gemm_mma_tf32(
    const float* __restrict__ A, const float* __restrict__ Bt,
    float* __restrict__ C, int K,
    long strideA, long strideB, long strideC, int roundC)
{
    extern __shared__ float smem[];
    const uint32_t sb = smem_u32(smem);
    // smem layout: A0 @0, A1 @16K, B0 @32K, B1 @48K  (bytes)
    const int tid  = threadIdx.x;
    const int wid  = tid >> 5;
    const int lane = tid & 31;
    const int bn   = blockIdx.x * 128;
    const int bm   = blockIdx.y * 128;
    const int bz   = blockIdx.z;
    A  += (long)bz * strideA;
    Bt += (long)bz * strideB;
    C  += (long)bz * strideC;

    const int wm = (wid & 1) * 64;    // warp m offset in CTA tile
    const int wn = (wid >> 1) * 32;   // warp n offset

    float acc[4][4][4];
#pragma unroll
    for (int a = 0; a < 4; a++)
#pragma unroll
        for (int b = 0; b < 4; b++)
#pragma unroll
            for (int c = 0; c < 4; c++) acc[a][b][c] = 0.f;

    const int nch = K / KC;

    // ---- chunk loader (A tile 128x32, B tile 128x32; 4 cp.async each/thread)
    auto load_chunk = [&](int i, int buf) {
        const uint32_t aBase = sb + (uint32_t)buf * 16384u;
        const uint32_t bBase = sb + 32768u + (uint32_t)buf * 16384u;
#pragma unroll
        for (int q = 0; q < 4; q++) {
            int f4 = tid + q * 256;
            int r  = f4 >> 3;
            int cf = f4 & 7;
            const float* g = A + (long)(bm + r) * K + i * KC + cf * 4;
            cp16(aBase + (uint32_t)(r * 128 + 16 * (cf ^ (r & 7))), g);
        }
#pragma unroll
        for (int q = 0; q < 4; q++) {
            int f4 = tid + q * 256;
            int r  = f4 >> 3;
            int cf = f4 & 7;
            const float* g = Bt + (long)(bn + r) * K + i * KC + cf * 4;
            cp16(bBase + (uint32_t)(r * 128 + 16 * (cf ^ (r & 7))), g);
        }
    };

    // fragment address components
    const int tr   = lane & 7;
    const int sel  = lane >> 3;        // 0..3
    const int aRow = (sel & 1) * 8;    // +8 row for matrices 1,3
    const int aKf  = sel >> 1;         // +1 kf4 for matrices 2,3
    const int bKf  = sel & 1;          // +1 kf4 for matrix 1 (x2)

    load_chunk(0, 0);
    cp_commit();

    for (int i = 0; i < nch; i++) {
        const int buf = i & 1;
        if (i + 1 < nch) {
            load_chunk(i + 1, buf ^ 1);
            cp_commit();
            cp_wait<1>();
        } else {
            cp_wait<0>();
        }
        __syncthreads();

        const uint32_t aB = sb + (uint32_t)buf * 16384u;
        const uint32_t bB = sb + 32768u + (uint32_t)buf * 16384u;

#pragma unroll
        for (int ks = 0; ks < 4; ks++) {
            uint32_t ar[4][4];
#pragma unroll
            for (int mt = 0; mt < 4; mt++) {
                int row = wm + mt * 16 + aRow + tr;
                uint32_t addr = aB + (uint32_t)(row * 128 + 16 * (((ks << 1) + aKf) ^ (row & 7)));
                ldsm_x4(ar[mt], addr);
            }
            uint32_t br[4][2];
#pragma unroll
            for (int nt = 0; nt < 4; nt++) {
                int row = wn + nt * 8 + tr;
                uint32_t addr = bB + (uint32_t)(row * 128 + 16 * (((ks << 1) + bKf) ^ (row & 7)));
                ldsm_x2(br[nt], addr);
            }
#pragma unroll
            for (int mt = 0; mt < 4; mt++)
#pragma unroll
                for (int nt = 0; nt < 4; nt++)
                    mma_tf32(acc[mt][nt], ar[mt], br[nt]);
        }
        __syncthreads();
    }

    // ---- epilogue: c0,c1 at (row, col..col+1), c2,c3 at (row+8, ...)
#pragma unroll
    for (int mt = 0; mt < 4; mt++) {
#pragma unroll
        for (int nt = 0; nt < 4; nt++) {
            int r0  = bm + wm + mt * 16 + (lane >> 2);
            int c0i = bn + wn + nt * 8 + 2 * (lane & 3);
            float2 v0, v1;
            v0.x = acc[mt][nt][0]; v0.y = acc[mt][nt][1];
            v1.x = acc[mt][nt][2]; v1.y = acc[mt][nt][3];
            if (roundC) {
                v0.x = tf32r(v0.x); v0.y = tf32r(v0.y);
                v1.x = tf32r(v1.x); v1.y = tf32r(v1.y);
            }
            *(float2*)(C + (long)r0 * 256 + c0i)       = v0;
            *(float2*)(C + (long)(r0 + 8) * 256 + c0i) = v1;
        }
    }
}

// ---------------------------------------------------------------------------
// Kernel 4: fused bias + LayerNorm + ReLU (+ optional residual)
// ---------------------------------------------------------------------------
__global__ __launch_bounds__(256) void ln_act_kernel(
    const float* __restrict__ Z, const float* __restrict__ bias,
    const float* __restrict__ gamma, const float* __restrict__ beta,
    const float* __restrict__ residual, float* __restrict__ out)
{
    const long row = blockIdx.x;
    const int j = threadIdx.x;
    const long idx = row * HH + j;

    float z = Z[idx] + bias[j];

    float s = z, q = z * z;
#pragma unroll
    for (int o = 16; o > 0; o >>= 1) {
        s += __shfl_down_sync(0xffffffffu, s, o);
        q += __shfl_down_sync(0xffffffffu, q, o);
    }
    __shared__ float2 sbuf[8];
    int lane = threadIdx.x & 31, wid = threadIdx.x >> 5;
    if (lane == 0) sbuf[wid] = make_float2(s, q);
    __syncthreads();
    if (wid == 0) {
        float2 p = (lane < 8) ? sbuf[lane] : make_float2(0.f, 0.f);
#pragma unroll
        for (int o = 4; o > 0; o >>= 1) {
            p.x += __shfl_down_sync(0xffffffffu, p.x, o);
            p.y += __shfl_down_sync(0xffffffffu, p.y, o);
        }
        if (lane == 0) sbuf[0] = p;
    }
    __syncthreads();
    const float mu  = sbuf[0].x * (1.0f / HH);
    const float var = sbuf[0].y * (1.0f / HH) - mu * mu;
    const float rstd = rsqrtf(var + LN_EPS);

    float y = (z - mu) * rstd * gamma[j] + beta[j];
    y = fmaxf(y, 0.0f);
    if (residual) y += residual[idx];
    out[idx] = y;
}

// ---------------------------------------------------------------------------
// Launch orchestration (graph-capturable)
// ---------------------------------------------------------------------------
extern "C" void kernel_launch(void* const* d_in, const int* in_sizes, int n_in,
                              void* d_out, int out_size)
{
    const float* node_feat = (const float*)d_in[0];   // [B,N,F]
    const float* edge_w    = (const float*)d_in[1];   // [B,N,N]
    const float* adj       = (const float*)d_in[2];   // [B,N,N]
    const float* W_in      = (const float*)d_in[3];   // [F,H]
    const float* b_in      = (const float*)d_in[4];   // [H]
    const float* g_in      = (const float*)d_in[5];   // [H]
    const float* bt_in     = (const float*)d_in[6];   // [H]
    const float* W         = (const float*)d_in[7];   // [L,H,H]
    const float* bvec      = (const float*)d_in[8];   // [L,H]
    const float* gamma     = (const float*)d_in[9];   // [L,H]
    const float* beta      = (const float*)d_in[10];  // [L,H]
    float* out = (float*)d_out;                       // [B,N,H]

    float *na_p, *nf_p, *h_p, *hT_p, *agg_p, *tmp_p, *wT_p;
    cudaGetSymbolAddress((void**)&na_p,  g_norm_adj);
    cudaGetSymbolAddress((void**)&nf_p,  g_nf);
    cudaGetSymbolAddress((void**)&h_p,   g_h);
    cudaGetSymbolAddress((void**)&hT_p,  g_hT);
    cudaGetSymbolAddress((void**)&agg_p, g_agg);
    cudaGetSymbolAddress((void**)&tmp_p, g_tmp);
    cudaGetSymbolAddress((void**)&wT_p,  g_wT);

    const int GEMM_SMEM = 65536;
    cudaFuncSetAttribute(gemm_mma_tf32, cudaFuncAttributeMaxDynamicSharedMemorySize, GEMM_SMEM);

    const int M_all = BB * NN;                        // 16384
    float* winT = wT_p;                               // [256, 512]
    float* wlT  = wT_p + 256 * 512;                   // [3][256][256]

    // 1. normalized adjacency (tf32-rounded)
    norm_adj_kernel<<<dim3(NN, BB), 256>>>(adj, edge_w, na_p);

    // 2. weight transposes (tf32-rounded outputs)
    transpose_kernel<<<dim3(HH / 32, FF / 32, 1), dim3(32, 8)>>>(
        W_in, winT, FF, HH, 0, 0);
    transpose_kernel<<<dim3(HH / 32, HH / 32, LL), dim3(32, 8)>>>(
        W, wlT, HH, HH, (long)HH * HH, (long)HH * HH);

    // 3. tf32-round node_feat into dedicated g_nf (33.5 MB — sized correctly!)
    round_copy_kernel<<<(int)(((long)M_all * FF / 4) / 256), 256>>>(
        (const float4*)node_feat, (float4*)nf_p);

    // 4. input projection: tmp = nf_rounded @ W_in
    gemm_mma_tf32<<<dim3(HH / 128, M_all / 128, 1), 256, GEMM_SMEM>>>(
        nf_p, winT, tmp_p, FF, 0, 0, 0, 0);

    // 5. h = relu(LN(tmp + b_in))
    ln_act_kernel<<<M_all, 256>>>(tmp_p, b_in, g_in, bt_in, nullptr, h_p);

    // 6. GNN layers
    for (int l = 0; l < LL; l++) {
        // hT[b] = round_tf32(h[b]^T)
        transpose_kernel<<<dim3(HH / 32, NN / 32, BB), dim3(32, 8)>>>(
            h_p, hT_p, NN, HH, (long)NN * HH, (long)HH * NN);

        // agg[b] = norm_adj[b] @ h[b]   (output tf32-rounded: it's GEMM2's A)
        gemm_mma_tf32<<<dim3(HH / 128, NN / 128, BB), 256, GEMM_SMEM>>>(
            na_p, hT_p, agg_p, NN,
            (long)NN * NN, (long)HH * NN, (long)NN * HH, 1);

        // tmp = agg @ W[l]
        gemm_mma_tf32<<<dim3(HH / 128, M_all / 128, 1), 256, GEMM_SMEM>>>(
            agg_p, wlT + (long)l * HH * HH, tmp_p, HH, 0, 0, 0, 0);

        // h = relu(LN(tmp + b[l])) + h   (last layer -> d_out)
        float* dst = (l == LL - 1) ? out : h_p;
        ln_act_kernel<<<M_all, 256>>>(
            tmp_p, bvec + (long)l * HH, gamma + (long)l * HH,
            beta + (long)l * HH, h_p, dst);
    }
}

// round 5
// speedup vs baseline: 3.5297x; 1.0666x over previous
#include <cuda_runtime.h>
#include <math.h>
#include <stdint.h>

// Problem constants
#define BB 8
#define NN 2048
#define FF 512
#define HH 256
#define LL 3
#define LN_EPS 1e-5f

// ---------------------------------------------------------------------------
// Device scratch (static — no cudaMalloc allowed)
// ---------------------------------------------------------------------------
__device__ __align__(128) float g_norm_adj[(size_t)BB * NN * NN];  // 134 MB (tf32-rounded)
__device__ __align__(128) float g_nf[(size_t)BB * NN * FF];        // 33.5 MB (tf32-rounded node_feat)
__device__ __align__(128) float g_h[(size_t)BB * NN * HH];         // fp32
__device__ __align__(128) float g_hT[(size_t)BB * HH * NN];        // tf32-rounded
__device__ __align__(128) float g_agg[(size_t)BB * NN * HH];       // tf32-rounded (GEMM1 out)
__device__ __align__(128) float g_tmp[(size_t)BB * NN * HH];       // fp32
__device__ __align__(128) float g_wT[256 * 512 + 3 * 256 * 256];   // tf32-rounded W_in^T, W[l]^T

// ---------------------------------------------------------------------------
// Helpers
// ---------------------------------------------------------------------------
__device__ __forceinline__ float tf32r(float x) {
    uint32_t u;
    asm("cvt.rna.tf32.f32 %0, %1;" : "=r"(u) : "f"(x));
    return __uint_as_float(u);
}

__device__ __forceinline__ uint32_t smem_u32(const void* p) {
    uint32_t a;
    asm("{ .reg .u64 t; cvta.to.shared.u64 t, %1; cvt.u32.u64 %0, t; }" : "=r"(a) : "l"(p));
    return a;
}

__device__ __forceinline__ void cp16(uint32_t dst, const void* src) {
    asm volatile("cp.async.cg.shared.global [%0], [%1], 16;" :: "r"(dst), "l"(src) : "memory");
}
__device__ __forceinline__ void cp_commit() {
    asm volatile("cp.async.commit_group;" ::: "memory");
}
template <int N> __device__ __forceinline__ void cp_wait() {
    asm volatile("cp.async.wait_group %0;" :: "n"(N) : "memory");
}

__device__ __forceinline__ void ldsm_x4(uint32_t* r, uint32_t addr) {
    asm volatile("ldmatrix.sync.aligned.m8n8.x4.shared.b16 {%0,%1,%2,%3}, [%4];"
                 : "=r"(r[0]), "=r"(r[1]), "=r"(r[2]), "=r"(r[3]) : "r"(addr));
}
__device__ __forceinline__ void ldsm_x2(uint32_t* r, uint32_t addr) {
    asm volatile("ldmatrix.sync.aligned.m8n8.x2.shared.b16 {%0,%1}, [%2];"
                 : "=r"(r[0]), "=r"(r[1]) : "r"(addr));
}

__device__ __forceinline__ void mma_tf32(float* c, const uint32_t* a, const uint32_t* b) {
    asm volatile("mma.sync.aligned.m16n8k8.row.col.f32.tf32.tf32.f32 "
                 "{%0,%1,%2,%3}, {%4,%5,%6,%7}, {%8,%9}, {%0,%1,%2,%3};"
                 : "+f"(c[0]), "+f"(c[1]), "+f"(c[2]), "+f"(c[3])
                 : "r"(a[0]), "r"(a[1]), "r"(a[2]), "r"(a[3]), "r"(b[0]), "r"(b[1]));
}

// ---------------------------------------------------------------------------
// Kernel 1: normalized adjacency (tf32-rounded; GEMM1's A operand). float4.
// ---------------------------------------------------------------------------
__global__ __launch_bounds__(256) void norm_adj_kernel(
    const float4* __restrict__ adj, const float4* __restrict__ ew,
    float4* __restrict__ out)
{
    const int row = blockIdx.x;
    const int b   = blockIdx.y;
    const long base4 = ((long)b * NN + row) * (NN / 4);
    const float4* __restrict__ arow = adj + base4;
    const float4* __restrict__ erow = ew + base4;
    float4* __restrict__ orow = out + base4;

    __shared__ float4 w4[NN / 4];
    __shared__ float sbuf[8];

    const int diag4 = row >> 2;   // float4 index containing the diagonal
    const int diagc = row & 3;

    float lsum = 0.f;
#pragma unroll
    for (int i = 0; i < 2; i++) {
        int c4 = threadIdx.x + i * 256;
        float4 a = arow[c4];
        float4 e = erow[c4];
        if (c4 == diag4) {
            if (diagc == 0) a.x += 1.f;
            else if (diagc == 1) a.y += 1.f;
            else if (diagc == 2) a.z += 1.f;
            else a.w += 1.f;
        }
        float4 v;
        v.x = fminf(a.x, 1.f) * e.x;
        v.y = fminf(a.y, 1.f) * e.y;
        v.z = fminf(a.z, 1.f) * e.z;
        v.w = fminf(a.w, 1.f) * e.w;
        w4[c4] = v;
        lsum += v.x + v.y + v.z + v.w;
    }
#pragma unroll
    for (int o = 16; o > 0; o >>= 1) lsum += __shfl_down_sync(0xffffffffu, lsum, o);
    int lane = threadIdx.x & 31, wid = threadIdx.x >> 5;
    if (lane == 0) sbuf[wid] = lsum;
    __syncthreads();
    if (wid == 0) {
        float v = (lane < 8) ? sbuf[lane] : 0.f;
#pragma unroll
        for (int o = 4; o > 0; o >>= 1) v += __shfl_down_sync(0xffffffffu, v, o);
        if (lane == 0) sbuf[0] = v;
    }
    __syncthreads();
    const float inv = 1.0f / (sbuf[0] + 1e-8f);

#pragma unroll
    for (int i = 0; i < 2; i++) {
        int c4 = threadIdx.x + i * 256;
        float4 v = w4[c4];
        v.x = tf32r(v.x * inv);
        v.y = tf32r(v.y * inv);
        v.z = tf32r(v.z * inv);
        v.w = tf32r(v.w * inv);
        orow[c4] = v;
    }
}

// ---------------------------------------------------------------------------
// Kernel 2: 32x32 transpose with tf32 rounding (weights only now)
// ---------------------------------------------------------------------------
__global__ __launch_bounds__(256) void transpose_kernel(
    const float* __restrict__ in, float* __restrict__ out,
    int R, int C, long sIn, long sOut)
{
    __shared__ float tile[32][33];
    const int bz = blockIdx.z;
    in  += (long)bz * sIn;
    out += (long)bz * sOut;
    const int c0 = blockIdx.x * 32;
    const int r0 = blockIdx.y * 32;
    const int tx = threadIdx.x, ty = threadIdx.y;
#pragma unroll
    for (int i = 0; i < 4; i++)
        tile[ty + i * 8][tx] = in[(long)(r0 + ty + i * 8) * C + c0 + tx];
    __syncthreads();
#pragma unroll
    for (int i = 0; i < 4; i++)
        out[(long)(c0 + ty + i * 8) * R + r0 + tx] = tf32r(tile[tx][ty + i * 8]);
}

// ---------------------------------------------------------------------------
// Kernel 2b: elementwise tf32 rounding copy (node_feat -> g_nf)
// ---------------------------------------------------------------------------
__global__ __launch_bounds__(256) void round_copy_kernel(
    const float4* __restrict__ in, float4* __restrict__ out)
{
    long i = (long)blockIdx.x * 256 + threadIdx.x;
    float4 v = in[i];
    v.x = tf32r(v.x); v.y = tf32r(v.y); v.z = tf32r(v.z); v.w = tf32r(v.w);
    out[i] = v;
}

// ---------------------------------------------------------------------------
// Kernel 3: TF32 tensor-core GEMM (mma.sync), CTA tile 128x256 (full H).
// C[bm:bm+128, 0:256] = A[M,K] @ Bt[256,K]^T   (ldc = 256)
// 512 threads = 16 warps (2m x 8n), warp tile 64x32, Kc=32, 3-stage cp.async.
// grid: (M/128, batch). K % 32 == 0, K >= 64. Inputs tf32-pre-rounded.
// ---------------------------------------------------------------------------
#define KC 32
__global__ __launch_bounds__(512, 1) void gemm_mma_tf32(
    const float* __restrict__ A, const float* __restrict__ Bt,
    float* __restrict__ C, int K,
    long strideA, long strideB, long strideC, int roundC)
{
    extern __shared__ float smem[];
    const uint32_t sb = smem_u32(smem);
    // smem: A bufs 3 x 16KB @ 0; B bufs 3 x 32KB @ 49152. total 147456 B.
    const int tid  = threadIdx.x;
    const int wid  = tid >> 5;
    const int lane = tid & 31;
    const int bm   = blockIdx.x * 128;
    const int bz   = blockIdx.y;
    A  += (long)bz * strideA;
    Bt += (long)bz * strideB;
    C  += (long)bz * strideC;

    const int wm = (wid & 1) * 64;    // warp m offset
    const int wn = (wid >> 1) * 32;   // warp n offset (0..224)

    float acc[4][4][4];
#pragma unroll
    for (int a = 0; a < 4; a++)
#pragma unroll
        for (int b = 0; b < 4; b++)
#pragma unroll
            for (int c = 0; c < 4; c++) acc[a][b][c] = 0.f;

    const int nch = K / KC;

    // chunk loader: A tile 128x32 (2 cp16/thread), B tile 256x32 (4 cp16/thread)
    auto load_chunk = [&](int i, int buf) {
        const uint32_t aBase = sb + (uint32_t)buf * 16384u;
        const uint32_t bBase = sb + 49152u + (uint32_t)buf * 32768u;
#pragma unroll
        for (int q = 0; q < 2; q++) {
            int f4 = tid + q * 512;
            int r  = f4 >> 3;
            int cf = f4 & 7;
            cp16(aBase + (uint32_t)(r * 128 + 16 * (cf ^ (r & 7))),
                 A + (long)(bm + r) * K + i * KC + cf * 4);
        }
#pragma unroll
        for (int q = 0; q < 4; q++) {
            int f4 = tid + q * 512;
            int r  = f4 >> 3;
            int cf = f4 & 7;
            cp16(bBase + (uint32_t)(r * 128 + 16 * (cf ^ (r & 7))),
                 Bt + (long)r * K + i * KC + cf * 4);
        }
    };

    // fragment address components
    const int tr   = lane & 7;
    const int sel  = lane >> 3;        // 0..3
    const int aRow = (sel & 1) * 8;
    const int aKf  = sel >> 1;
    const int bKf  = sel & 1;

    load_chunk(0, 0); cp_commit();
    load_chunk(1, 1); cp_commit();

    int bufc = 0;                       // buffer index of chunk i (i % 3)
    for (int i = 0; i < nch; i++) {
        if (i + 2 < nch) {
            int bufn = bufc + 2; if (bufn >= 3) bufn -= 3;
            load_chunk(i + 2, bufn);
        }
        cp_commit();
        cp_wait<2>();
        __syncthreads();

        const uint32_t aB = sb + (uint32_t)bufc * 16384u;
        const uint32_t bB = sb + 49152u + (uint32_t)bufc * 32768u;

#pragma unroll
        for (int ks = 0; ks < 4; ks++) {
            uint32_t ar[4][4];
#pragma unroll
            for (int mt = 0; mt < 4; mt++) {
                int row = wm + mt * 16 + aRow + tr;
                uint32_t addr = aB + (uint32_t)(row * 128 + 16 * (((ks << 1) + aKf) ^ (row & 7)));
                ldsm_x4(ar[mt], addr);
            }
            uint32_t br[4][2];
#pragma unroll
            for (int nt = 0; nt < 4; nt++) {
                int row = wn + nt * 8 + tr;
                uint32_t addr = bB + (uint32_t)(row * 128 + 16 * (((ks << 1) + bKf) ^ (row & 7)));
                ldsm_x2(br[nt], addr);
            }
#pragma unroll
            for (int mt = 0; mt < 4; mt++)
#pragma unroll
                for (int nt = 0; nt < 4; nt++)
                    mma_tf32(acc[mt][nt], ar[mt], br[nt]);
        }
        __syncthreads();
        bufc++; if (bufc == 3) bufc = 0;
    }

    // epilogue
#pragma unroll
    for (int mt = 0; mt < 4; mt++) {
#pragma unroll
        for (int nt = 0; nt < 4; nt++) {
            int r0  = bm + wm + mt * 16 + (lane >> 2);
            int c0i = wn + nt * 8 + 2 * (lane & 3);
            float2 v0, v1;
            v0.x = acc[mt][nt][0]; v0.y = acc[mt][nt][1];
            v1.x = acc[mt][nt][2]; v1.y = acc[mt][nt][3];
            if (roundC) {
                v0.x = tf32r(v0.x); v0.y = tf32r(v0.y);
                v1.x = tf32r(v1.x); v1.y = tf32r(v1.y);
            }
            *(float2*)(C + (long)r0 * 256 + c0i)       = v0;
            *(float2*)(C + (long)(r0 + 8) * 256 + c0i) = v1;
        }
    }
}

// ---------------------------------------------------------------------------
// Kernel 4: fused bias + LayerNorm + ReLU (+ residual) + transposed tf32 copy.
// 32 rows per block, 256 threads (8 warps x 4 rows each).
// out[r][c] = relu(LN(Z[r]+bias)[c]) (+ residual[r][c])
// if outT: outT[b][c][r%2048] = tf32r(out[r][c])
// ---------------------------------------------------------------------------
__global__ __launch_bounds__(256) void ln_act_t_kernel(
    const float* __restrict__ Z, const float* __restrict__ bias,
    const float* __restrict__ gamma, const float* __restrict__ beta,
    const float* __restrict__ residual, float* __restrict__ out,
    float* __restrict__ outT)
{
    __shared__ float tile[256][33];   // [col][local_row]
    const int r0   = blockIdx.x * 32;
    const int warp = threadIdx.x >> 5;
    const int lane = threadIdx.x & 31;
    const bool doT = (outT != nullptr);

#pragma unroll
    for (int i = 0; i < 4; i++) {
        const int r  = r0 + warp * 4 + i;
        const int lr = r - r0;
        const float* zr = Z + (long)r * HH;
        float v[8];
        float s = 0.f, q = 0.f;
#pragma unroll
        for (int k = 0; k < 8; k++) {
            int c = lane + 32 * k;
            float z = zr[c] + bias[c];
            v[k] = z; s += z; q += z * z;
        }
#pragma unroll
        for (int o = 16; o > 0; o >>= 1) {
            s += __shfl_xor_sync(0xffffffffu, s, o);
            q += __shfl_xor_sync(0xffffffffu, q, o);
        }
        const float mu   = s * (1.0f / HH);
        const float var  = q * (1.0f / HH) - mu * mu;
        const float rstd = rsqrtf(var + LN_EPS);

        float* orow = out + (long)r * HH;
        const float* rrow = residual ? residual + (long)r * HH : nullptr;
#pragma unroll
        for (int k = 0; k < 8; k++) {
            int c = lane + 32 * k;
            float y = (v[k] - mu) * rstd * gamma[c] + beta[c];
            y = fmaxf(y, 0.0f);
            if (rrow) y += rrow[c];
            orow[c] = y;
            if (doT) tile[c][lr] = tf32r(y);
        }
    }

    if (doT) {
        __syncthreads();
        const int c    = threadIdx.x;
        const int b    = r0 >> 11;        // / NN
        const int rloc = r0 & (NN - 1);
        float* dst = outT + ((long)b * HH + c) * NN + rloc;
#pragma unroll
        for (int g = 0; g < 8; g++) {
            float4 w;
            w.x = tile[c][4 * g + 0];
            w.y = tile[c][4 * g + 1];
            w.z = tile[c][4 * g + 2];
            w.w = tile[c][4 * g + 3];
            *(float4*)(dst + 4 * g) = w;
        }
    }
}

// ---------------------------------------------------------------------------
// Launch orchestration (graph-capturable)
// ---------------------------------------------------------------------------
extern "C" void kernel_launch(void* const* d_in, const int* in_sizes, int n_in,
                              void* d_out, int out_size)
{
    const float* node_feat = (const float*)d_in[0];   // [B,N,F]
    const float* edge_w    = (const float*)d_in[1];   // [B,N,N]
    const float* adj       = (const float*)d_in[2];   // [B,N,N]
    const float* W_in      = (const float*)d_in[3];   // [F,H]
    const float* b_in      = (const float*)d_in[4];   // [H]
    const float* g_in      = (const float*)d_in[5];   // [H]
    const float* bt_in     = (const float*)d_in[6];   // [H]
    const float* W         = (const float*)d_in[7];   // [L,H,H]
    const float* bvec      = (const float*)d_in[8];   // [L,H]
    const float* gamma     = (const float*)d_in[9];   // [L,H]
    const float* beta      = (const float*)d_in[10];  // [L,H]
    float* out = (float*)d_out;                       // [B,N,H]

    float *na_p, *nf_p, *h_p, *hT_p, *agg_p, *tmp_p, *wT_p;
    cudaGetSymbolAddress((void**)&na_p,  g_norm_adj);
    cudaGetSymbolAddress((void**)&nf_p,  g_nf);
    cudaGetSymbolAddress((void**)&h_p,   g_h);
    cudaGetSymbolAddress((void**)&hT_p,  g_hT);
    cudaGetSymbolAddress((void**)&agg_p, g_agg);
    cudaGetSymbolAddress((void**)&tmp_p, g_tmp);
    cudaGetSymbolAddress((void**)&wT_p,  g_wT);

    const int GEMM_SMEM = 147456;
    cudaFuncSetAttribute(gemm_mma_tf32, cudaFuncAttributeMaxDynamicSharedMemorySize, GEMM_SMEM);

    const int M_all = BB * NN;                        // 16384
    float* winT = wT_p;                               // [256, 512]
    float* wlT  = wT_p + 256 * 512;                   // [3][256][256]

    // 1. normalized adjacency (tf32-rounded)
    norm_adj_kernel<<<dim3(NN, BB), 256>>>(
        (const float4*)adj, (const float4*)edge_w, (float4*)na_p);

    // 2. weight transposes (tf32-rounded outputs)
    transpose_kernel<<<dim3(HH / 32, FF / 32, 1), dim3(32, 8)>>>(
        W_in, winT, FF, HH, 0, 0);
    transpose_kernel<<<dim3(HH / 32, HH / 32, LL), dim3(32, 8)>>>(
        W, wlT, HH, HH, (long)HH * HH, (long)HH * HH);

    // 3. tf32-round node_feat into g_nf
    round_copy_kernel<<<(int)(((long)M_all * FF / 4) / 256), 256>>>(
        (const float4*)node_feat, (float4*)nf_p);

    // 4. input projection: tmp = nf @ W_in   (N tile = 256 = full H)
    gemm_mma_tf32<<<dim3(M_all / 128, 1), 512, GEMM_SMEM>>>(
        nf_p, winT, tmp_p, FF, 0, 0, 0, 0);

    // 5. h = relu(LN(tmp + b_in)); also hT (tf32-rounded)
    ln_act_t_kernel<<<M_all / 32, 256>>>(tmp_p, b_in, g_in, bt_in, nullptr, h_p, hT_p);

    // 6. GNN layers
    for (int l = 0; l < LL; l++) {
        // agg[b] = norm_adj[b] @ h[b]   (tf32-rounded out: GEMM2's A operand)
        gemm_mma_tf32<<<dim3(NN / 128, BB), 512, GEMM_SMEM>>>(
            na_p, hT_p, agg_p, NN,
            (long)NN * NN, (long)HH * NN, (long)NN * HH, 1);

        // tmp = agg @ W[l]
        gemm_mma_tf32<<<dim3(M_all / 128, 1), 512, GEMM_SMEM>>>(
            agg_p, wlT + (long)l * HH * HH, tmp_p, HH, 0, 0, 0, 0);

        // h = relu(LN(tmp + b[l])) + h  (+ hT for next layer; last layer -> out)
        float* dst  = (l == LL - 1) ? out : h_p;
        float* dstT = (l == LL - 1) ? nullptr : hT_p;
        ln_act_t_kernel<<<M_all / 32, 256>>>(
            tmp_p, bvec + (long)l * HH, gamma + (long)l * HH,
            beta + (long)l * HH, h_p, dst, dstT);
    }
}

// round 6
// speedup vs baseline: 5.5440x; 1.5707x over previous
#include <cuda_runtime.h>
#include <cuda_fp16.h>
#include <math.h>
#include <stdint.h>

// Problem constants
#define BB 8
#define NN 2048
#define FF 512
#define HH 256
#define LL 3
#define LN_EPS 1e-5f

// ---------------------------------------------------------------------------
// Device scratch (static — no cudaMalloc allowed)
// ---------------------------------------------------------------------------
__device__ __align__(128) __half g_norm_adj[(size_t)BB * NN * NN];   // 67 MB
__device__ __align__(128) __half g_nf[(size_t)BB * NN * FF];         // 16.8 MB
__device__ __align__(128) float  g_h[(size_t)BB * NN * HH];          // 16.8 MB fp32 (residual)
__device__ __align__(128) __half g_hT[(size_t)BB * HH * NN];         // 8.4 MB
__device__ __align__(128) __half g_agg[(size_t)BB * NN * HH];        // 8.4 MB
__device__ __align__(128) float  g_tmp[(size_t)BB * NN * HH];        // 16.8 MB fp32 (LN input)
__device__ __align__(128) __half g_wT[256 * 512 + 3 * 256 * 256];    // W_in^T, W[l]^T (half)

// ---------------------------------------------------------------------------
// Helpers
// ---------------------------------------------------------------------------
__device__ __forceinline__ uint32_t smem_u32(const void* p) {
    uint32_t a;
    asm("{ .reg .u64 t; cvta.to.shared.u64 t, %1; cvt.u32.u64 %0, t; }" : "=r"(a) : "l"(p));
    return a;
}

__device__ __forceinline__ void cp16(uint32_t dst, const void* src) {
    asm volatile("cp.async.cg.shared.global [%0], [%1], 16;" :: "r"(dst), "l"(src) : "memory");
}
__device__ __forceinline__ void cp_commit() {
    asm volatile("cp.async.commit_group;" ::: "memory");
}
template <int N> __device__ __forceinline__ void cp_wait() {
    asm volatile("cp.async.wait_group %0;" :: "n"(N) : "memory");
}

__device__ __forceinline__ void ldsm_x4(uint32_t* r, uint32_t addr) {
    asm volatile("ldmatrix.sync.aligned.m8n8.x4.shared.b16 {%0,%1,%2,%3}, [%4];"
                 : "=r"(r[0]), "=r"(r[1]), "=r"(r[2]), "=r"(r[3]) : "r"(addr));
}
__device__ __forceinline__ void ldsm_x2(uint32_t* r, uint32_t addr) {
    asm volatile("ldmatrix.sync.aligned.m8n8.x2.shared.b16 {%0,%1}, [%2];"
                 : "=r"(r[0]), "=r"(r[1]) : "r"(addr));
}

// m16n8k16 fp16 MMA with fp32 accumulate
__device__ __forceinline__ void mma_f16(float* c, const uint32_t* a, const uint32_t* b) {
    asm volatile("mma.sync.aligned.m16n8k16.row.col.f32.f16.f16.f32 "
                 "{%0,%1,%2,%3}, {%4,%5,%6,%7}, {%8,%9}, {%0,%1,%2,%3};"
                 : "+f"(c[0]), "+f"(c[1]), "+f"(c[2]), "+f"(c[3])
                 : "r"(a[0]), "r"(a[1]), "r"(a[2]), "r"(a[3]), "r"(b[0]), "r"(b[1]));
}

// ---------------------------------------------------------------------------
// Kernel 1: normalized adjacency -> fp16 (GEMM1's A operand). float4 reads.
// ---------------------------------------------------------------------------
__global__ __launch_bounds__(256) void norm_adj_kernel(
    const float4* __restrict__ adj, const float4* __restrict__ ew,
    __half* __restrict__ out)
{
    const int row = blockIdx.x;
    const int b   = blockIdx.y;
    const long base4 = ((long)b * NN + row) * (NN / 4);
    const float4* __restrict__ arow = adj + base4;
    const float4* __restrict__ erow = ew + base4;
    __half2* __restrict__ orow = (__half2*)(out + ((long)b * NN + row) * NN);

    __shared__ float4 w4[NN / 4];
    __shared__ float sbuf[8];

    const int diag4 = row >> 2;
    const int diagc = row & 3;

    float lsum = 0.f;
#pragma unroll
    for (int i = 0; i < 2; i++) {
        int c4 = threadIdx.x + i * 256;
        float4 a = arow[c4];
        float4 e = erow[c4];
        if (c4 == diag4) {
            if (diagc == 0) a.x += 1.f;
            else if (diagc == 1) a.y += 1.f;
            else if (diagc == 2) a.z += 1.f;
            else a.w += 1.f;
        }
        float4 v;
        v.x = fminf(a.x, 1.f) * e.x;
        v.y = fminf(a.y, 1.f) * e.y;
        v.z = fminf(a.z, 1.f) * e.z;
        v.w = fminf(a.w, 1.f) * e.w;
        w4[c4] = v;
        lsum += v.x + v.y + v.z + v.w;
    }
#pragma unroll
    for (int o = 16; o > 0; o >>= 1) lsum += __shfl_down_sync(0xffffffffu, lsum, o);
    int lane = threadIdx.x & 31, wid = threadIdx.x >> 5;
    if (lane == 0) sbuf[wid] = lsum;
    __syncthreads();
    if (wid == 0) {
        float v = (lane < 8) ? sbuf[lane] : 0.f;
#pragma unroll
        for (int o = 4; o > 0; o >>= 1) v += __shfl_down_sync(0xffffffffu, v, o);
        if (lane == 0) sbuf[0] = v;
    }
    __syncthreads();
    const float inv = 1.0f / (sbuf[0] + 1e-8f);

#pragma unroll
    for (int i = 0; i < 2; i++) {
        int c4 = threadIdx.x + i * 256;
        float4 v = w4[c4];
        orow[2 * c4 + 0] = __floats2half2_rn(v.x * inv, v.y * inv);
        orow[2 * c4 + 1] = __floats2half2_rn(v.z * inv, v.w * inv);
    }
}

// ---------------------------------------------------------------------------
// Kernel 2: 32x32 transpose, fp32 in -> fp16 out (weights)
// ---------------------------------------------------------------------------
__global__ __launch_bounds__(256) void transpose_kernel(
    const float* __restrict__ in, __half* __restrict__ out,
    int R, int C, long sIn, long sOut)
{
    __shared__ float tile[32][33];
    const int bz = blockIdx.z;
    in  += (long)bz * sIn;
    out += (long)bz * sOut;
    const int c0 = blockIdx.x * 32;
    const int r0 = blockIdx.y * 32;
    const int tx = threadIdx.x, ty = threadIdx.y;
#pragma unroll
    for (int i = 0; i < 4; i++)
        tile[ty + i * 8][tx] = in[(long)(r0 + ty + i * 8) * C + c0 + tx];
    __syncthreads();
#pragma unroll
    for (int i = 0; i < 4; i++)
        out[(long)(c0 + ty + i * 8) * R + r0 + tx] = __float2half_rn(tile[tx][ty + i * 8]);
}

// ---------------------------------------------------------------------------
// Kernel 2b: fp32 -> fp16 copy (node_feat -> g_nf)
// ---------------------------------------------------------------------------
__global__ __launch_bounds__(256) void half_copy_kernel(
    const float4* __restrict__ in, __half2* __restrict__ out)
{
    long i = (long)blockIdx.x * 256 + threadIdx.x;
    float4 v = in[i];
    out[2 * i + 0] = __floats2half2_rn(v.x, v.y);
    out[2 * i + 1] = __floats2half2_rn(v.z, v.w);
}

// ---------------------------------------------------------------------------
// Kernel 3: FP16 tensor-core GEMM (mma.sync m16n8k16), CTA tile 128x256.
// C[bm:bm+128, 0:256] = A[M,K] @ Bt[256,K]^T  (ldc = 256; fp32 accumulate)
// 512 threads = 16 warps (2m x 8n), warp tile 64x32, Kc=64 halfs (128B rows),
// 3-stage cp.async. grid (M/128, batch). K % 64 == 0. outHalf: C dtype.
// ---------------------------------------------------------------------------
#define KC 64
__global__ __launch_bounds__(512, 1) void gemm_mma_f16(
    const __half* __restrict__ A, const __half* __restrict__ Bt,
    void* __restrict__ Cv, int K,
    long strideA, long strideB, long strideC, int outHalf)
{
    extern __shared__ float smem[];
    const uint32_t sb = smem_u32(smem);
    // smem: A bufs 3 x 16KB @ 0; B bufs 3 x 32KB @ 49152. total 147456 B.
    const int tid  = threadIdx.x;
    const int wid  = tid >> 5;
    const int lane = tid & 31;
    const int bm   = blockIdx.x * 128;
    const int bz   = blockIdx.y;
    A  += (long)bz * strideA;
    Bt += (long)bz * strideB;

    const int wm = (wid & 1) * 64;
    const int wn = (wid >> 1) * 32;

    float acc[4][4][4];
#pragma unroll
    for (int a = 0; a < 4; a++)
#pragma unroll
        for (int b = 0; b < 4; b++)
#pragma unroll
            for (int c = 0; c < 4; c++) acc[a][b][c] = 0.f;

    const int nch = K / KC;

    // A tile 128x64h (2 cp16/thread), B tile 256x64h (4 cp16/thread)
    auto load_chunk = [&](int i, int buf) {
        const uint32_t aBase = sb + (uint32_t)buf * 16384u;
        const uint32_t bBase = sb + 49152u + (uint32_t)buf * 32768u;
#pragma unroll
        for (int q = 0; q < 2; q++) {
            int f8 = tid + q * 512;
            int r  = f8 >> 3;
            int cf = f8 & 7;
            cp16(aBase + (uint32_t)(r * 128 + 16 * (cf ^ (r & 7))),
                 A + (long)(bm + r) * K + i * KC + cf * 8);
        }
#pragma unroll
        for (int q = 0; q < 4; q++) {
            int f8 = tid + q * 512;
            int r  = f8 >> 3;
            int cf = f8 & 7;
            cp16(bBase + (uint32_t)(r * 128 + 16 * (cf ^ (r & 7))),
                 Bt + (long)r * K + i * KC + cf * 8);
        }
    };

    // fragment address components (identical algebra to the verified tf32 path;
    // 16B unit = 8 halfs here)
    const int tr   = lane & 7;
    const int sel  = lane >> 3;        // 0..3
    const int aRow = (sel & 1) * 8;    // matrices 1,3: rows +8
    const int aKf  = sel >> 1;         // matrices 2,3: k +8 halfs (+1 unit)
    const int bKf  = sel & 1;          // x2: matrix 1 is k +8 halfs

    load_chunk(0, 0); cp_commit();
    load_chunk(1, 1); cp_commit();

    int bufc = 0;
    for (int i = 0; i < nch; i++) {
        if (i + 2 < nch) {
            int bufn = bufc + 2; if (bufn >= 3) bufn -= 3;
            load_chunk(i + 2, bufn);
        }
        cp_commit();
        cp_wait<2>();
        __syncthreads();

        const uint32_t aB = sb + (uint32_t)bufc * 16384u;
        const uint32_t bB = sb + 49152u + (uint32_t)bufc * 32768u;

#pragma unroll
        for (int ks = 0; ks < 4; ks++) {   // 4 x k16 = 64 halfs
            uint32_t ar[4][4];
#pragma unroll
            for (int mt = 0; mt < 4; mt++) {
                int row = wm + mt * 16 + aRow + tr;
                uint32_t addr = aB + (uint32_t)(row * 128 + 16 * (((ks << 1) + aKf) ^ (row & 7)));
                ldsm_x4(ar[mt], addr);
            }
            uint32_t br[4][2];
#pragma unroll
            for (int nt = 0; nt < 4; nt++) {
                int row = wn + nt * 8 + tr;
                uint32_t addr = bB + (uint32_t)(row * 128 + 16 * (((ks << 1) + bKf) ^ (row & 7)));
                ldsm_x2(br[nt], addr);
            }
#pragma unroll
            for (int mt = 0; mt < 4; mt++)
#pragma unroll
                for (int nt = 0; nt < 4; nt++)
                    mma_f16(acc[mt][nt], ar[mt], br[nt]);
        }
        __syncthreads();
        bufc++; if (bufc == 3) bufc = 0;
    }

    // epilogue: c0,c1 at (row, col..col+1), c2,c3 at (row+8, ...)
    if (outHalf) {
        __half* C = (__half*)Cv + (long)bz * strideC;
#pragma unroll
        for (int mt = 0; mt < 4; mt++) {
#pragma unroll
            for (int nt = 0; nt < 4; nt++) {
                int r0  = bm + wm + mt * 16 + (lane >> 2);
                int c0i = wn + nt * 8 + 2 * (lane & 3);
                *(__half2*)(C + (long)r0 * 256 + c0i) =
                    __floats2half2_rn(acc[mt][nt][0], acc[mt][nt][1]);
                *(__half2*)(C + (long)(r0 + 8) * 256 + c0i) =
                    __floats2half2_rn(acc[mt][nt][2], acc[mt][nt][3]);
            }
        }
    } else {
        float* C = (float*)Cv + (long)bz * strideC;
#pragma unroll
        for (int mt = 0; mt < 4; mt++) {
#pragma unroll
            for (int nt = 0; nt < 4; nt++) {
                int r0  = bm + wm + mt * 16 + (lane >> 2);
                int c0i = wn + nt * 8 + 2 * (lane & 3);
                float2 v0, v1;
                v0.x = acc[mt][nt][0]; v0.y = acc[mt][nt][1];
                v1.x = acc[mt][nt][2]; v1.y = acc[mt][nt][3];
                *(float2*)(C + (long)r0 * 256 + c0i)       = v0;
                *(float2*)(C + (long)(r0 + 8) * 256 + c0i) = v1;
            }
        }
    }
}

// ---------------------------------------------------------------------------
// Kernel 4: fused bias + LayerNorm + ReLU (+ residual) + transposed fp16 copy.
// 32 rows per block, 256 threads (8 warps x 4 rows each).
// ---------------------------------------------------------------------------
__global__ __launch_bounds__(256) void ln_act_t_kernel(
    const float* __restrict__ Z, const float* __restrict__ bias,
    const float* __restrict__ gamma, const float* __restrict__ beta,
    const float* __restrict__ residual, float* __restrict__ out,
    __half* __restrict__ outT)
{
    __shared__ __half tile[256][40];   // [col][local_row], 80B row stride
    const int r0   = blockIdx.x * 32;
    const int warp = threadIdx.x >> 5;
    const int lane = threadIdx.x & 31;
    const bool doT = (outT != nullptr);

#pragma unroll
    for (int i = 0; i < 4; i++) {
        const int r  = r0 + warp * 4 + i;
        const int lr = r - r0;
        const float* zr = Z + (long)r * HH;
        float v[8];
        float s = 0.f, q = 0.f;
#pragma unroll
        for (int k = 0; k < 8; k++) {
            int c = lane + 32 * k;
            float z = zr[c] + bias[c];
            v[k] = z; s += z; q += z * z;
        }
#pragma unroll
        for (int o = 16; o > 0; o >>= 1) {
            s += __shfl_xor_sync(0xffffffffu, s, o);
            q += __shfl_xor_sync(0xffffffffu, q, o);
        }
        const float mu   = s * (1.0f / HH);
        const float var  = q * (1.0f / HH) - mu * mu;
        const float rstd = rsqrtf(var + LN_EPS);

        float* orow = out + (long)r * HH;
        const float* rrow = residual ? residual + (long)r * HH : nullptr;
#pragma unroll
        for (int k = 0; k < 8; k++) {
            int c = lane + 32 * k;
            float y = (v[k] - mu) * rstd * gamma[c] + beta[c];
            y = fmaxf(y, 0.0f);
            if (rrow) y += rrow[c];
            orow[c] = y;
            if (doT) tile[c][lr] = __float2half_rn(y);
        }
    }

    if (doT) {
        __syncthreads();
        const int c    = threadIdx.x;
        const int b    = r0 >> 11;        // / NN
        const int rloc = r0 & (NN - 1);
        __half* dst = outT + ((long)b * HH + c) * NN + rloc;
        const uint4* src = (const uint4*)&tile[c][0];   // 32 halfs = 4x16B
#pragma unroll
        for (int g = 0; g < 4; g++)
            ((uint4*)dst)[g] = src[g];
    }
}

// ---------------------------------------------------------------------------
// Launch orchestration (graph-capturable)
// ---------------------------------------------------------------------------
extern "C" void kernel_launch(void* const* d_in, const int* in_sizes, int n_in,
                              void* d_out, int out_size)
{
    const float* node_feat = (const float*)d_in[0];   // [B,N,F]
    const float* edge_w    = (const float*)d_in[1];   // [B,N,N]
    const float* adj       = (const float*)d_in[2];   // [B,N,N]
    const float* W_in      = (const float*)d_in[3];   // [F,H]
    const float* b_in      = (const float*)d_in[4];   // [H]
    const float* g_in      = (const float*)d_in[5];   // [H]
    const float* bt_in     = (const float*)d_in[6];   // [H]
    const float* W         = (const float*)d_in[7];   // [L,H,H]
    const float* bvec      = (const float*)d_in[8];   // [L,H]
    const float* gamma     = (const float*)d_in[9];   // [L,H]
    const float* beta      = (const float*)d_in[10];  // [L,H]
    float* out = (float*)d_out;                       // [B,N,H]

    __half *na_p, *nf_p, *hT_p, *agg_p, *wT_p;
    float *h_p, *tmp_p;
    cudaGetSymbolAddress((void**)&na_p,  g_norm_adj);
    cudaGetSymbolAddress((void**)&nf_p,  g_nf);
    cudaGetSymbolAddress((void**)&h_p,   g_h);
    cudaGetSymbolAddress((void**)&hT_p,  g_hT);
    cudaGetSymbolAddress((void**)&agg_p, g_agg);
    cudaGetSymbolAddress((void**)&tmp_p, g_tmp);
    cudaGetSymbolAddress((void**)&wT_p,  g_wT);

    const int GEMM_SMEM = 147456;
    cudaFuncSetAttribute(gemm_mma_f16, cudaFuncAttributeMaxDynamicSharedMemorySize, GEMM_SMEM);

    const int M_all = BB * NN;                        // 16384
    __half* winT = wT_p;                              // [256, 512]
    __half* wlT  = wT_p + 256 * 512;                  // [3][256][256]

    // 1. normalized adjacency -> fp16
    norm_adj_kernel<<<dim3(NN, BB), 256>>>(
        (const float4*)adj, (const float4*)edge_w, na_p);

    // 2. weight transposes -> fp16
    transpose_kernel<<<dim3(HH / 32, FF / 32, 1), dim3(32, 8)>>>(
        W_in, winT, FF, HH, 0, 0);
    transpose_kernel<<<dim3(HH / 32, HH / 32, LL), dim3(32, 8)>>>(
        W, wlT, HH, HH, (long)HH * HH, (long)HH * HH);

    // 3. node_feat -> fp16
    half_copy_kernel<<<(int)(((long)M_all * FF / 4) / 256), 256>>>(
        (const float4*)node_feat, (__half2*)nf_p);

    // 4. input projection: tmp = nf @ W_in  (fp32 out)
    gemm_mma_f16<<<dim3(M_all / 128, 1), 512, GEMM_SMEM>>>(
        nf_p, winT, tmp_p, FF, 0, 0, 0, 0);

    // 5. h = relu(LN(tmp + b_in)); also hT (fp16)
    ln_act_t_kernel<<<M_all / 32, 256>>>(tmp_p, b_in, g_in, bt_in, nullptr, h_p, hT_p);

    // 6. GNN layers
    for (int l = 0; l < LL; l++) {
        // agg[b] = norm_adj[b] @ h[b]   (fp16 out: GEMM2's A operand)
        gemm_mma_f16<<<dim3(NN / 128, BB), 512, GEMM_SMEM>>>(
            na_p, hT_p, agg_p, NN,
            (long)NN * NN, (long)HH * NN, (long)NN * HH, 1);

        // tmp = agg @ W[l]  (fp32 out)
        gemm_mma_f16<<<dim3(M_all / 128, 1), 512, GEMM_SMEM>>>(
            agg_p, wlT + (long)l * HH * HH, tmp_p, HH, 0, 0, 0, 0);

        // h = relu(LN(tmp + b[l])) + h  (+ hT for next layer; last layer -> out)
        float* dst   = (l == LL - 1) ? out : h_p;
        __half* dstT = (l == LL - 1) ? nullptr : hT_p;
        ln_act_t_kernel<<<M_all / 32, 256>>>(
            tmp_p, bvec + (long)l * HH, gamma + (long)l * HH,
            beta + (long)l * HH, h_p, dst, dstT);
    }
}

// round 7
// speedup vs baseline: 5.7203x; 1.0318x over previous
#include <cuda_runtime.h>
#include <cuda_fp16.h>
#include <math.h>
#include <stdint.h>

// Problem constants
#define BB 8
#define NN 2048
#define FF 512
#define HH 256
#define LL 3
#define LN_EPS 1e-5f

// ---------------------------------------------------------------------------
// Device scratch (static — no cudaMalloc allowed)
// ---------------------------------------------------------------------------
__device__ __align__(128) __half g_norm_adj[(size_t)BB * NN * NN];   // 67 MB
__device__ __align__(128) __half g_nf[(size_t)BB * NN * FF];         // 16.8 MB
__device__ __align__(128) float  g_h[(size_t)BB * NN * HH];          // fp32 residual
__device__ __align__(128) __half g_hTa[(size_t)BB * HH * NN];        // hT ping
__device__ __align__(128) __half g_hTb[(size_t)BB * HH * NN];        // hT pong
__device__ __align__(128) float  g_tmp[(size_t)BB * NN * HH];        // proj output
__device__ __align__(128) __half g_wT[256 * 512 + 3 * 256 * 256];    // W_in^T, W[l]^T

// ---------------------------------------------------------------------------
// Helpers
// ---------------------------------------------------------------------------
__device__ __forceinline__ uint32_t smem_u32(const void* p) {
    uint32_t a;
    asm("{ .reg .u64 t; cvta.to.shared.u64 t, %1; cvt.u32.u64 %0, t; }" : "=r"(a) : "l"(p));
    return a;
}
__device__ __forceinline__ void cp16(uint32_t dst, const void* src) {
    asm volatile("cp.async.cg.shared.global [%0], [%1], 16;" :: "r"(dst), "l"(src) : "memory");
}
__device__ __forceinline__ void cp_commit() {
    asm volatile("cp.async.commit_group;" ::: "memory");
}
template <int N> __device__ __forceinline__ void cp_wait() {
    asm volatile("cp.async.wait_group %0;" :: "n"(N) : "memory");
}
__device__ __forceinline__ void ldsm_x4(uint32_t* r, uint32_t addr) {
    asm volatile("ldmatrix.sync.aligned.m8n8.x4.shared.b16 {%0,%1,%2,%3}, [%4];"
                 : "=r"(r[0]), "=r"(r[1]), "=r"(r[2]), "=r"(r[3]) : "r"(addr));
}
__device__ __forceinline__ void ldsm_x2(uint32_t* r, uint32_t addr) {
    asm volatile("ldmatrix.sync.aligned.m8n8.x2.shared.b16 {%0,%1}, [%2];"
                 : "=r"(r[0]), "=r"(r[1]) : "r"(addr));
}
__device__ __forceinline__ void mma_f16(float* c, const uint32_t* a, const uint32_t* b) {
    asm volatile("mma.sync.aligned.m16n8k16.row.col.f32.f16.f16.f32 "
                 "{%0,%1,%2,%3}, {%4,%5,%6,%7}, {%8,%9}, {%0,%1,%2,%3};"
                 : "+f"(c[0]), "+f"(c[1]), "+f"(c[2]), "+f"(c[3])
                 : "r"(a[0]), "r"(a[1]), "r"(a[2]), "r"(a[3]), "r"(b[0]), "r"(b[1]));
}

// ---------------------------------------------------------------------------
// Kernel 1: normalized adjacency -> fp16
// ---------------------------------------------------------------------------
__global__ __launch_bounds__(256) void norm_adj_kernel(
    const float4* __restrict__ adj, const float4* __restrict__ ew,
    __half* __restrict__ out)
{
    const int row = blockIdx.x;
    const int b   = blockIdx.y;
    const long base4 = ((long)b * NN + row) * (NN / 4);
    const float4* __restrict__ arow = adj + base4;
    const float4* __restrict__ erow = ew + base4;
    __half2* __restrict__ orow = (__half2*)(out + ((long)b * NN + row) * NN);

    __shared__ float4 w4[NN / 4];
    __shared__ float sbuf[8];

    const int diag4 = row >> 2;
    const int diagc = row & 3;

    float lsum = 0.f;
#pragma unroll
    for (int i = 0; i < 2; i++) {
        int c4 = threadIdx.x + i * 256;
        float4 a = arow[c4];
        float4 e = erow[c4];
        if (c4 == diag4) {
            if (diagc == 0) a.x += 1.f;
            else if (diagc == 1) a.y += 1.f;
            else if (diagc == 2) a.z += 1.f;
            else a.w += 1.f;
        }
        float4 v;
        v.x = fminf(a.x, 1.f) * e.x;
        v.y = fminf(a.y, 1.f) * e.y;
        v.z = fminf(a.z, 1.f) * e.z;
        v.w = fminf(a.w, 1.f) * e.w;
        w4[c4] = v;
        lsum += v.x + v.y + v.z + v.w;
    }
#pragma unroll
    for (int o = 16; o > 0; o >>= 1) lsum += __shfl_down_sync(0xffffffffu, lsum, o);
    int lane = threadIdx.x & 31, wid = threadIdx.x >> 5;
    if (lane == 0) sbuf[wid] = lsum;
    __syncthreads();
    if (wid == 0) {
        float v = (lane < 8) ? sbuf[lane] : 0.f;
#pragma unroll
        for (int o = 4; o > 0; o >>= 1) v += __shfl_down_sync(0xffffffffu, v, o);
        if (lane == 0) sbuf[0] = v;
    }
    __syncthreads();
    const float inv = 1.0f / (sbuf[0] + 1e-8f);

#pragma unroll
    for (int i = 0; i < 2; i++) {
        int c4 = threadIdx.x + i * 256;
        float4 v = w4[c4];
        orow[2 * c4 + 0] = __floats2half2_rn(v.x * inv, v.y * inv);
        orow[2 * c4 + 1] = __floats2half2_rn(v.z * inv, v.w * inv);
    }
}

// ---------------------------------------------------------------------------
// Kernel 2: 32x32 transpose, fp32 -> fp16 (weights)
// ---------------------------------------------------------------------------
__global__ __launch_bounds__(256) void transpose_kernel(
    const float* __restrict__ in, __half* __restrict__ out,
    int R, int C, long sIn, long sOut)
{
    __shared__ float tile[32][33];
    const int bz = blockIdx.z;
    in  += (long)bz * sIn;
    out += (long)bz * sOut;
    const int c0 = blockIdx.x * 32;
    const int r0 = blockIdx.y * 32;
    const int tx = threadIdx.x, ty = threadIdx.y;
#pragma unroll
    for (int i = 0; i < 4; i++)
        tile[ty + i * 8][tx] = in[(long)(r0 + ty + i * 8) * C + c0 + tx];
    __syncthreads();
#pragma unroll
    for (int i = 0; i < 4; i++)
        out[(long)(c0 + ty + i * 8) * R + r0 + tx] = __float2half_rn(tile[tx][ty + i * 8]);
}

// ---------------------------------------------------------------------------
// Kernel 2b: fp32 -> fp16 copy (node_feat)
// ---------------------------------------------------------------------------
__global__ __launch_bounds__(256) void half_copy_kernel(
    const float4* __restrict__ in, __half2* __restrict__ out)
{
    long i = (long)blockIdx.x * 256 + threadIdx.x;
    float4 v = in[i];
    out[2 * i + 0] = __floats2half2_rn(v.x, v.y);
    out[2 * i + 1] = __floats2half2_rn(v.z, v.w);
}

// ---------------------------------------------------------------------------
// Kernel 3: FP16 GEMM (input projection only). Same as round 6.
// ---------------------------------------------------------------------------
#define KC 64
__global__ __launch_bounds__(512, 1) void gemm_mma_f16(
    const __half* __restrict__ A, const __half* __restrict__ Bt,
    float* __restrict__ C, int K)
{
    extern __shared__ float smemf[];
    char* smem = (char*)smemf;
    const uint32_t sb = smem_u32(smem);
    const int tid  = threadIdx.x;
    const int wid  = tid >> 5;
    const int lane = tid & 31;
    const int bm   = blockIdx.x * 128;

    const int wm = (wid & 1) * 64;
    const int wn = (wid >> 1) * 32;

    float acc[4][4][4];
#pragma unroll
    for (int a = 0; a < 4; a++)
#pragma unroll
        for (int b = 0; b < 4; b++)
#pragma unroll
            for (int c = 0; c < 4; c++) acc[a][b][c] = 0.f;

    const int nch = K / KC;

    auto load_chunk = [&](int i, int buf) {
        const uint32_t aBase = sb + (uint32_t)buf * 16384u;
        const uint32_t bBase = sb + 49152u + (uint32_t)buf * 32768u;
#pragma unroll
        for (int q = 0; q < 2; q++) {
            int f8 = tid + q * 512;
            int r  = f8 >> 3;
            int cf = f8 & 7;
            cp16(aBase + (uint32_t)(r * 128 + 16 * (cf ^ (r & 7))),
                 A + (long)(bm + r) * K + i * KC + cf * 8);
        }
#pragma unroll
        for (int q = 0; q < 4; q++) {
            int f8 = tid + q * 512;
            int r  = f8 >> 3;
            int cf = f8 & 7;
            cp16(bBase + (uint32_t)(r * 128 + 16 * (cf ^ (r & 7))),
                 Bt + (long)r * K + i * KC + cf * 8);
        }
    };

    const int tr   = lane & 7;
    const int sel  = lane >> 3;
    const int aRow = (sel & 1) * 8;
    const int aKf  = sel >> 1;
    const int bKf  = sel & 1;

    load_chunk(0, 0); cp_commit();
    load_chunk(1, 1); cp_commit();

    int bufc = 0;
    for (int i = 0; i < nch; i++) {
        if (i + 2 < nch) {
            int bufn = bufc + 2; if (bufn >= 3) bufn -= 3;
            load_chunk(i + 2, bufn);
        }
        cp_commit();
        cp_wait<2>();
        __syncthreads();

        const uint32_t aB = sb + (uint32_t)bufc * 16384u;
        const uint32_t bB = sb + 49152u + (uint32_t)bufc * 32768u;

#pragma unroll
        for (int ks = 0; ks < 4; ks++) {
            uint32_t ar[4][4];
#pragma unroll
            for (int mt = 0; mt < 4; mt++) {
                int row = wm + mt * 16 + aRow + tr;
                ldsm_x4(ar[mt], aB + (uint32_t)(row * 128 + 16 * (((ks << 1) + aKf) ^ (row & 7))));
            }
            uint32_t br[4][2];
#pragma unroll
            for (int nt = 0; nt < 4; nt++) {
                int row = wn + nt * 8 + tr;
                ldsm_x2(br[nt], bB + (uint32_t)(row * 128 + 16 * (((ks << 1) + bKf) ^ (row & 7))));
            }
#pragma unroll
            for (int mt = 0; mt < 4; mt++)
#pragma unroll
                for (int nt = 0; nt < 4; nt++)
                    mma_f16(acc[mt][nt], ar[mt], br[nt]);
        }
        __syncthreads();
        bufc++; if (bufc == 3) bufc = 0;
    }

#pragma unroll
    for (int mt = 0; mt < 4; mt++) {
#pragma unroll
        for (int nt = 0; nt < 4; nt++) {
            int r0  = bm + wm + mt * 16 + (lane >> 2);
            int c0i = wn + nt * 8 + 2 * (lane & 3);
            float2 v0, v1;
            v0.x = acc[mt][nt][0]; v0.y = acc[mt][nt][1];
            v1.x = acc[mt][nt][2]; v1.y = acc[mt][nt][3];
            *(float2*)(C + (long)r0 * 256 + c0i)       = v0;
            *(float2*)(C + (long)(r0 + 8) * 256 + c0i) = v1;
        }
    }
}

// ---------------------------------------------------------------------------
// Kernel 4: fused bias + LN + ReLU + transposed fp16 copy (first LN only)
// ---------------------------------------------------------------------------
__global__ __launch_bounds__(256) void ln_act_t_kernel(
    const float* __restrict__ Z, const float* __restrict__ bias,
    const float* __restrict__ gamma, const float* __restrict__ beta,
    float* __restrict__ out, __half* __restrict__ outT)
{
    __shared__ __half tile[256][40];
    const int r0   = blockIdx.x * 32;
    const int warp = threadIdx.x >> 5;
    const int lane = threadIdx.x & 31;

#pragma unroll
    for (int i = 0; i < 4; i++) {
        const int r  = r0 + warp * 4 + i;
        const int lr = r - r0;
        const float* zr = Z + (long)r * HH;
        float v[8];
        float s = 0.f, q = 0.f;
#pragma unroll
        for (int k = 0; k < 8; k++) {
            int c = lane + 32 * k;
            float z = zr[c] + bias[c];
            v[k] = z; s += z; q += z * z;
        }
#pragma unroll
        for (int o = 16; o > 0; o >>= 1) {
            s += __shfl_xor_sync(0xffffffffu, s, o);
            q += __shfl_xor_sync(0xffffffffu, q, o);
        }
        const float mu   = s * (1.0f / HH);
        const float var  = q * (1.0f / HH) - mu * mu;
        const float rstd = rsqrtf(var + LN_EPS);

        float* orow = out + (long)r * HH;
#pragma unroll
        for (int k = 0; k < 8; k++) {
            int c = lane + 32 * k;
            float y = (v[k] - mu) * rstd * gamma[c] + beta[c];
            y = fmaxf(y, 0.0f);
            orow[c] = y;
            tile[c][lr] = __float2half_rn(y);
        }
    }

    __syncthreads();
    const int c    = threadIdx.x;
    const int b    = r0 >> 11;
    const int rloc = r0 & (NN - 1);
    __half* dst = outT + ((long)b * HH + c) * NN + rloc;
    const uint4* src = (const uint4*)&tile[c][0];
#pragma unroll
    for (int g = 0; g < 4; g++)
        ((uint4*)dst)[g] = src[g];
}

// ---------------------------------------------------------------------------
// Kernel 5: FUSED GNN LAYER.
// Per CTA (128 rows of one batch):
//   phase 1: agg = norm_adj[rows,:] @ h        (K=2048, acc fp32)
//   phase 2: tmp = agg(fp16) @ W[l]            (K=256, via smem restage)
//   phase 3: h_new = relu(LN(tmp+b)*g+be) + h  (cross-warp LN reduction)
//            write h_new (fp32) and optionally hT_new (fp16, transposed)
// grid (NN/128, BB), 512 threads = 16 warps (2m x 8n).
// smem: [0,147456): phase-1 pipeline (A 3x16K, B 3x32K); phase-2 B2 4x32K;
//       phase-3 hT tile.  [147456,+64K): A2 restage (4 chunks of 16K).
//       then s_part[128][8], q_part[128][8], mu[128], rstd[128].
// ---------------------------------------------------------------------------
#define A2_OFF    147456u
#define SP_OFF    (A2_OFF + 65536u)
#define QP_OFF    (SP_OFF + 4096u)
#define MU_OFF    (QP_OFF + 4096u)
#define RS_OFF    (MU_OFF + 512u)
#define FUSED_SMEM (RS_OFF + 512u)

__global__ __launch_bounds__(512, 1) void layer_fused(
    const __half* __restrict__ NA,     // [BB][NN][NN]
    const __half* __restrict__ hTin,   // [BB][HH][NN]
    const __half* __restrict__ Wt,     // [256][256] = W[l]^T
    const float* __restrict__ bias,
    const float* __restrict__ gamma,
    const float* __restrict__ beta,
    const float* __restrict__ hres,    // [BB][NN][HH] residual
    float* __restrict__ dstF,          // h (mid layers) or final out
    __half* __restrict__ hTout)        // next hT, or nullptr (last layer)
{
    extern __shared__ char smem[];
    const uint32_t sb = smem_u32(smem);
    const int tid  = threadIdx.x;
    const int wid  = tid >> 5;
    const int lane = tid & 31;
    const int bm   = blockIdx.x * 128;
    const int b    = blockIdx.y;

    const __half* A  = NA   + (size_t)b * NN * NN;
    const __half* Bt = hTin + (size_t)b * HH * NN;

    const int wm = (wid & 1) * 64;
    const int wn = (wid >> 1) * 32;
    const int tr   = lane & 7;
    const int sel  = lane >> 3;
    const int aRow = (sel & 1) * 8;
    const int aKf  = sel >> 1;
    const int bKf  = sel & 1;

    float acc[4][4][4];
#pragma unroll
    for (int a = 0; a < 4; a++)
#pragma unroll
        for (int x = 0; x < 4; x++)
#pragma unroll
            for (int c = 0; c < 4; c++) acc[a][x][c] = 0.f;

    // ================= phase 1: K = 2048 mainloop =================
    auto load_chunk = [&](int i, int buf) {
        const uint32_t aBase = sb + (uint32_t)buf * 16384u;
        const uint32_t bBase = sb + 49152u + (uint32_t)buf * 32768u;
#pragma unroll
        for (int q = 0; q < 2; q++) {
            int f8 = tid + q * 512;
            int r  = f8 >> 3;
            int cf = f8 & 7;
            cp16(aBase + (uint32_t)(r * 128 + 16 * (cf ^ (r & 7))),
                 A + (long)(bm + r) * NN + i * KC + cf * 8);
        }
#pragma unroll
        for (int q = 0; q < 4; q++) {
            int f8 = tid + q * 512;
            int r  = f8 >> 3;
            int cf = f8 & 7;
            cp16(bBase + (uint32_t)(r * 128 + 16 * (cf ^ (r & 7))),
                 Bt + (long)r * NN + i * KC + cf * 8);
        }
    };

    load_chunk(0, 0); cp_commit();
    load_chunk(1, 1); cp_commit();

    const int nch = NN / KC;   // 32
    int bufc = 0;
    for (int i = 0; i < nch; i++) {
        if (i + 2 < nch) {
            int bufn = bufc + 2; if (bufn >= 3) bufn -= 3;
            load_chunk(i + 2, bufn);
        }
        cp_commit();
        cp_wait<2>();
        __syncthreads();

        const uint32_t aB = sb + (uint32_t)bufc * 16384u;
        const uint32_t bB = sb + 49152u + (uint32_t)bufc * 32768u;
#pragma unroll
        for (int ks = 0; ks < 4; ks++) {
            uint32_t ar[4][4];
#pragma unroll
            for (int mt = 0; mt < 4; mt++) {
                int row = wm + mt * 16 + aRow + tr;
                ldsm_x4(ar[mt], aB + (uint32_t)(row * 128 + 16 * (((ks << 1) + aKf) ^ (row & 7))));
            }
            uint32_t br[4][2];
#pragma unroll
            for (int nt = 0; nt < 4; nt++) {
                int row = wn + nt * 8 + tr;
                ldsm_x2(br[nt], bB + (uint32_t)(row * 128 + 16 * (((ks << 1) + bKf) ^ (row & 7))));
            }
#pragma unroll
            for (int mt = 0; mt < 4; mt++)
#pragma unroll
                for (int nt = 0; nt < 4; nt++)
                    mma_f16(acc[mt][nt], ar[mt], br[nt]);
        }
        __syncthreads();
        bufc++; if (bufc == 3) bufc = 0;
    }

    // ================= phase 2 staging =================
    // B2: W[l]^T [256 n][256 k] into 4 chunk buffers at region0 (k-chunks of 64)
#pragma unroll
    for (int q = 0; q < 16; q++) {
        int u     = tid + q * 512;        // 16B-unit index, 0..8191
        int chunk = u >> 11;              // 2048 units per chunk
        int v     = u & 2047;
        int r     = v >> 3;               // n row 0..255
        int cf    = v & 7;
        cp16(sb + (uint32_t)(chunk * 32768 + r * 128 + 16 * (cf ^ (r & 7))),
             Wt + (long)r * 256 + chunk * 64 + cf * 8);
    }
    cp_commit();

    // A2: acc -> fp16 smem in chunk layout (cols are now K)
    {
        const uint32_t a2base = sb + A2_OFF + (uint32_t)(wn >> 6) * 16384u;
        const int ubase = (wn & 32) >> 3;
        const uint32_t coff = (uint32_t)(4 * (lane & 3));
#pragma unroll
        for (int mt = 0; mt < 4; mt++) {
            int rlo = wm + mt * 16 + (lane >> 2);
            int rhi = rlo + 8;
#pragma unroll
            for (int nt = 0; nt < 4; nt++) {
                int u = ubase + nt;
                uint32_t alo = a2base + (uint32_t)(rlo * 128 + 16 * (u ^ (rlo & 7))) + coff;
                uint32_t ahi = a2base + (uint32_t)(rhi * 128 + 16 * (u ^ (rhi & 7))) + coff;
                __half2 lo = __floats2half2_rn(acc[mt][nt][0], acc[mt][nt][1]);
                __half2 hi = __floats2half2_rn(acc[mt][nt][2], acc[mt][nt][3]);
                *(__half2*)(smem + (alo - sb)) = lo;
                *(__half2*)(smem + (ahi - sb)) = hi;
            }
        }
    }
    cp_wait<0>();
    __syncthreads();

    // ================= phase 2 mainloop: K = 256, 4 resident chunks ========
    float acc2[4][4][4];
#pragma unroll
    for (int a = 0; a < 4; a++)
#pragma unroll
        for (int x = 0; x < 4; x++)
#pragma unroll
            for (int c = 0; c < 4; c++) acc2[a][x][c] = 0.f;

#pragma unroll
    for (int i = 0; i < 4; i++) {
        const uint32_t aB = sb + A2_OFF + (uint32_t)i * 16384u;
        const uint32_t bB = sb + (uint32_t)i * 32768u;
#pragma unroll
        for (int ks = 0; ks < 4; ks++) {
            uint32_t ar[4][4];
#pragma unroll
            for (int mt = 0; mt < 4; mt++) {
                int row = wm + mt * 16 + aRow + tr;
                ldsm_x4(ar[mt], aB + (uint32_t)(row * 128 + 16 * (((ks << 1) + aKf) ^ (row & 7))));
            }
            uint32_t br[4][2];
#pragma unroll
            for (int nt = 0; nt < 4; nt++) {
                int row = wn + nt * 8 + tr;
                ldsm_x2(br[nt], bB + (uint32_t)(row * 128 + 16 * (((ks << 1) + bKf) ^ (row & 7))));
            }
#pragma unroll
            for (int mt = 0; mt < 4; mt++)
#pragma unroll
                for (int nt = 0; nt < 4; nt++)
                    mma_f16(acc2[mt][nt], ar[mt], br[nt]);
        }
    }
    __syncthreads();   // region0 + A2 free for epilogue reuse

    // ================= phase 3: LN epilogue =================
    float* spart = (float*)(smem + SP_OFF);   // [128][8]
    float* qpart = (float*)(smem + QP_OFF);
    float* muS   = (float*)(smem + MU_OFF);
    float* rsS   = (float*)(smem + RS_OFF);
    const int wni = wid >> 1;

#pragma unroll
    for (int mt = 0; mt < 4; mt++) {
        float sl = 0.f, ql = 0.f, sh = 0.f, qh = 0.f;
#pragma unroll
        for (int nt = 0; nt < 4; nt++) {
            int c0 = wn + nt * 8 + 2 * (lane & 3);
            float b0 = bias[c0], b1 = bias[c0 + 1];
            float z0 = acc2[mt][nt][0] + b0;
            float z1 = acc2[mt][nt][1] + b1;
            float z2 = acc2[mt][nt][2] + b0;
            float z3 = acc2[mt][nt][3] + b1;
            acc2[mt][nt][0] = z0; acc2[mt][nt][1] = z1;
            acc2[mt][nt][2] = z2; acc2[mt][nt][3] = z3;
            sl += z0 + z1; ql += z0 * z0 + z1 * z1;
            sh += z2 + z3; qh += z2 * z2 + z3 * z3;
        }
        sl += __shfl_xor_sync(0xffffffffu, sl, 1);
        sl += __shfl_xor_sync(0xffffffffu, sl, 2);
        ql += __shfl_xor_sync(0xffffffffu, ql, 1);
        ql += __shfl_xor_sync(0xffffffffu, ql, 2);
        sh += __shfl_xor_sync(0xffffffffu, sh, 1);
        sh += __shfl_xor_sync(0xffffffffu, sh, 2);
        qh += __shfl_xor_sync(0xffffffffu, qh, 1);
        qh += __shfl_xor_sync(0xffffffffu, qh, 2);
        if ((lane & 3) == 0) {
            int rlo = wm + mt * 16 + (lane >> 2);
            spart[rlo * 8 + wni] = sl;
            qpart[rlo * 8 + wni] = ql;
            spart[(rlo + 8) * 8 + wni] = sh;
            qpart[(rlo + 8) * 8 + wni] = qh;
        }
    }
    __syncthreads();
    if (tid < 128) {
        float s = 0.f, q = 0.f;
#pragma unroll
        for (int j = 0; j < 8; j++) { s += spart[tid * 8 + j]; q += qpart[tid * 8 + j]; }
        float mu  = s * (1.0f / HH);
        float var = q * (1.0f / HH) - mu * mu;
        muS[tid] = mu;
        rsS[tid] = rsqrtf(var + LN_EPS);
    }
    __syncthreads();

    __half* tile = (__half*)smem;   // [256 cols][136 rows] halfs
    const bool doT = (hTout != nullptr);
    const float* hr = hres + ((size_t)b * NN + bm) * HH;
    float* df       = dstF + ((size_t)b * NN + bm) * HH;

#pragma unroll
    for (int mt = 0; mt < 4; mt++) {
        int rl = wm + mt * 16 + (lane >> 2);
        int rh = rl + 8;
        float mul = muS[rl], rsl = rsS[rl];
        float muh = muS[rh], rsh = rsS[rh];
#pragma unroll
        for (int nt = 0; nt < 4; nt++) {
            int c0 = wn + nt * 8 + 2 * (lane & 3);
            float g0 = gamma[c0], g1 = gamma[c0 + 1];
            float e0 = beta[c0],  e1 = beta[c0 + 1];
            float y0 = fmaxf((acc2[mt][nt][0] - mul) * rsl * g0 + e0, 0.f) + hr[(long)rl * HH + c0];
            float y1 = fmaxf((acc2[mt][nt][1] - mul) * rsl * g1 + e1, 0.f) + hr[(long)rl * HH + c0 + 1];
            float y2 = fmaxf((acc2[mt][nt][2] - muh) * rsh * g0 + e0, 0.f) + hr[(long)rh * HH + c0];
            float y3 = fmaxf((acc2[mt][nt][3] - muh) * rsh * g1 + e1, 0.f) + hr[(long)rh * HH + c0 + 1];
            float2 vlo; vlo.x = y0; vlo.y = y1;
            float2 vhi; vhi.x = y2; vhi.y = y3;
            *(float2*)(df + (long)rl * HH + c0) = vlo;
            *(float2*)(df + (long)rh * HH + c0) = vhi;
            if (doT) {
                tile[(c0)     * 136 + rl] = __float2half_rn(y0);
                tile[(c0 + 1) * 136 + rl] = __float2half_rn(y1);
                tile[(c0)     * 136 + rh] = __float2half_rn(y2);
                tile[(c0 + 1) * 136 + rh] = __float2half_rn(y3);
            }
        }
    }

    if (doT) {
        __syncthreads();
        int c  = tid & 255;
        int hs = tid >> 8;   // 0 or 1: rows [0,64) / [64,128)
        __half* dst = hTout + ((size_t)b * HH + c) * NN + bm + hs * 64;
        const uint4* src = (const uint4*)(tile + c * 136 + hs * 64);
#pragma unroll
        for (int g = 0; g < 8; g++)
            ((uint4*)dst)[g] = src[g];
    }
}

// ---------------------------------------------------------------------------
// Launch orchestration (graph-capturable)
// ---------------------------------------------------------------------------
extern "C" void kernel_launch(void* const* d_in, const int* in_sizes, int n_in,
                              void* d_out, int out_size)
{
    const float* node_feat = (const float*)d_in[0];
    const float* edge_w    = (const float*)d_in[1];
    const float* adj       = (const float*)d_in[2];
    const float* W_in      = (const float*)d_in[3];
    const float* b_in      = (const float*)d_in[4];
    const float* g_in      = (const float*)d_in[5];
    const float* bt_in     = (const float*)d_in[6];
    const float* W         = (const float*)d_in[7];
    const float* bvec      = (const float*)d_in[8];
    const float* gamma     = (const float*)d_in[9];
    const float* beta      = (const float*)d_in[10];
    float* out = (float*)d_out;

    __half *na_p, *nf_p, *hTa_p, *hTb_p, *wT_p;
    float *h_p, *tmp_p;
    cudaGetSymbolAddress((void**)&na_p,  g_norm_adj);
    cudaGetSymbolAddress((void**)&nf_p,  g_nf);
    cudaGetSymbolAddress((void**)&h_p,   g_h);
    cudaGetSymbolAddress((void**)&hTa_p, g_hTa);
    cudaGetSymbolAddress((void**)&hTb_p, g_hTb);
    cudaGetSymbolAddress((void**)&tmp_p, g_tmp);
    cudaGetSymbolAddress((void**)&wT_p,  g_wT);

    cudaFuncSetAttribute(gemm_mma_f16, cudaFuncAttributeMaxDynamicSharedMemorySize, 147456);
    cudaFuncSetAttribute(layer_fused,  cudaFuncAttributeMaxDynamicSharedMemorySize, FUSED_SMEM);

    const int M_all = BB * NN;
    __half* winT = wT_p;
    __half* wlT  = wT_p + 256 * 512;

    // 1. normalized adjacency -> fp16
    norm_adj_kernel<<<dim3(NN, BB), 256>>>(
        (const float4*)adj, (const float4*)edge_w, na_p);

    // 2. weight transposes -> fp16
    transpose_kernel<<<dim3(HH / 32, FF / 32, 1), dim3(32, 8)>>>(
        W_in, winT, FF, HH, 0, 0);
    transpose_kernel<<<dim3(HH / 32, HH / 32, LL), dim3(32, 8)>>>(
        W, wlT, HH, HH, (long)HH * HH, (long)HH * HH);

    // 3. node_feat -> fp16
    half_copy_kernel<<<(int)(((long)M_all * FF / 4) / 256), 256>>>(
        (const float4*)node_feat, (__half2*)nf_p);

    // 4. input projection
    gemm_mma_f16<<<dim3(M_all / 128, 1), 512, 147456>>>(nf_p, winT, tmp_p, FF);

    // 5. first LN -> h (fp32) + hT_a (fp16)
    ln_act_t_kernel<<<M_all / 32, 256>>>(tmp_p, b_in, g_in, bt_in, h_p, hTa_p);

    // 6. fused GNN layers with hT ping-pong
    __half* hT_cur = hTa_p;
    __half* hT_nxt = hTb_p;
    for (int l = 0; l < LL; l++) {
        const bool last = (l == LL - 1);
        layer_fused<<<dim3(NN / 128, BB), 512, FUSED_SMEM>>>(
            na_p, hT_cur, wlT + (long)l * HH * HH,
            bvec + (long)l * HH, gamma + (long)l * HH, beta + (long)l * HH,
            h_p,
            last ? out : h_p,
            last ? nullptr : hT_nxt);
        __half* t = hT_cur; hT_cur = hT_nxt; hT_nxt = t;
    }
}

// round 8
// speedup vs baseline: 5.7933x; 1.0128x over previous
#include <cuda_runtime.h>
#include <cuda_fp16.h>
#include <math.h>
#include <stdint.h>

// Problem constants
#define BB 8
#define NN 2048
#define FF 512
#define HH 256
#define LL 3
#define LN_EPS 1e-5f

// ---------------------------------------------------------------------------
// Device scratch (static — no cudaMalloc allowed)
// ---------------------------------------------------------------------------
__device__ __align__(128) __half g_norm_adj[(size_t)BB * NN * NN];   // 67 MB
__device__ __align__(128) __half g_nf[(size_t)BB * NN * FF];         // 16.8 MB
__device__ __align__(128) float  g_h[(size_t)BB * NN * HH];          // fp32 residual
__device__ __align__(128) __half g_hTa[(size_t)BB * HH * NN];        // hT ping
__device__ __align__(128) __half g_hTb[(size_t)BB * HH * NN];        // hT pong
__device__ __align__(128) __half g_wT[256 * 512 + 3 * 256 * 256];    // W_in^T, W[l]^T

// ---------------------------------------------------------------------------
// Helpers
// ---------------------------------------------------------------------------
__device__ __forceinline__ uint32_t smem_u32(const void* p) {
    uint32_t a;
    asm("{ .reg .u64 t; cvta.to.shared.u64 t, %1; cvt.u32.u64 %0, t; }" : "=r"(a) : "l"(p));
    return a;
}
__device__ __forceinline__ void cp16(uint32_t dst, const void* src) {
    asm volatile("cp.async.cg.shared.global [%0], [%1], 16;" :: "r"(dst), "l"(src) : "memory");
}
__device__ __forceinline__ void cp_commit() {
    asm volatile("cp.async.commit_group;" ::: "memory");
}
template <int N> __device__ __forceinline__ void cp_wait() {
    asm volatile("cp.async.wait_group %0;" :: "n"(N) : "memory");
}
__device__ __forceinline__ void ldsm_x4(uint32_t* r, uint32_t addr) {
    asm volatile("ldmatrix.sync.aligned.m8n8.x4.shared.b16 {%0,%1,%2,%3}, [%4];"
                 : "=r"(r[0]), "=r"(r[1]), "=r"(r[2]), "=r"(r[3]) : "r"(addr));
}
__device__ __forceinline__ void ldsm_x2(uint32_t* r, uint32_t addr) {
    asm volatile("ldmatrix.sync.aligned.m8n8.x2.shared.b16 {%0,%1}, [%2];"
                 : "=r"(r[0]), "=r"(r[1]) : "r"(addr));
}
__device__ __forceinline__ void mma_f16(float* c, const uint32_t* a, const uint32_t* b) {
    asm volatile("mma.sync.aligned.m16n8k16.row.col.f32.f16.f16.f32 "
                 "{%0,%1,%2,%3}, {%4,%5,%6,%7}, {%8,%9}, {%0,%1,%2,%3};"
                 : "+f"(c[0]), "+f"(c[1]), "+f"(c[2]), "+f"(c[3])
                 : "r"(a[0]), "r"(a[1]), "r"(a[2]), "r"(a[3]), "r"(b[0]), "r"(b[1]));
}

// smem region offsets for fused kernels
#define KC 64
#define A2_OFF    147456u
#define SP_OFF    (A2_OFF + 65536u)
#define QP_OFF    (SP_OFF + 4096u)
#define MU_OFF    (QP_OFF + 4096u)
#define RS_OFF    (MU_OFF + 512u)
#define FUSED_SMEM (RS_OFF + 512u)

// ---------------------------------------------------------------------------
// Kernel 1: normalized adjacency -> fp16
// ---------------------------------------------------------------------------
__global__ __launch_bounds__(256) void norm_adj_kernel(
    const float4* __restrict__ adj, const float4* __restrict__ ew,
    __half* __restrict__ out)
{
    const int row = blockIdx.x;
    const int b   = blockIdx.y;
    const long base4 = ((long)b * NN + row) * (NN / 4);
    const float4* __restrict__ arow = adj + base4;
    const float4* __restrict__ erow = ew + base4;
    __half2* __restrict__ orow = (__half2*)(out + ((long)b * NN + row) * NN);

    __shared__ float4 w4[NN / 4];
    __shared__ float sbuf[8];

    const int diag4 = row >> 2;
    const int diagc = row & 3;

    float lsum = 0.f;
#pragma unroll
    for (int i = 0; i < 2; i++) {
        int c4 = threadIdx.x + i * 256;
        float4 a = arow[c4];
        float4 e = erow[c4];
        if (c4 == diag4) {
            if (diagc == 0) a.x += 1.f;
            else if (diagc == 1) a.y += 1.f;
            else if (diagc == 2) a.z += 1.f;
            else a.w += 1.f;
        }
        float4 v;
        v.x = fminf(a.x, 1.f) * e.x;
        v.y = fminf(a.y, 1.f) * e.y;
        v.z = fminf(a.z, 1.f) * e.z;
        v.w = fminf(a.w, 1.f) * e.w;
        w4[c4] = v;
        lsum += v.x + v.y + v.z + v.w;
    }
#pragma unroll
    for (int o = 16; o > 0; o >>= 1) lsum += __shfl_down_sync(0xffffffffu, lsum, o);
    int lane = threadIdx.x & 31, wid = threadIdx.x >> 5;
    if (lane == 0) sbuf[wid] = lsum;
    __syncthreads();
    if (wid == 0) {
        float v = (lane < 8) ? sbuf[lane] : 0.f;
#pragma unroll
        for (int o = 4; o > 0; o >>= 1) v += __shfl_down_sync(0xffffffffu, v, o);
        if (lane == 0) sbuf[0] = v;
    }
    __syncthreads();
    const float inv = 1.0f / (sbuf[0] + 1e-8f);

#pragma unroll
    for (int i = 0; i < 2; i++) {
        int c4 = threadIdx.x + i * 256;
        float4 v = w4[c4];
        orow[2 * c4 + 0] = __floats2half2_rn(v.x * inv, v.y * inv);
        orow[2 * c4 + 1] = __floats2half2_rn(v.z * inv, v.w * inv);
    }
}

// ---------------------------------------------------------------------------
// Kernel 2: 32x32 transpose, fp32 -> fp16 (weights)
// ---------------------------------------------------------------------------
__global__ __launch_bounds__(256) void transpose_kernel(
    const float* __restrict__ in, __half* __restrict__ out,
    int R, int C, long sIn, long sOut)
{
    __shared__ float tile[32][33];
    const int bz = blockIdx.z;
    in  += (long)bz * sIn;
    out += (long)bz * sOut;
    const int c0 = blockIdx.x * 32;
    const int r0 = blockIdx.y * 32;
    const int tx = threadIdx.x, ty = threadIdx.y;
#pragma unroll
    for (int i = 0; i < 4; i++)
        tile[ty + i * 8][tx] = in[(long)(r0 + ty + i * 8) * C + c0 + tx];
    __syncthreads();
#pragma unroll
    for (int i = 0; i < 4; i++)
        out[(long)(c0 + ty + i * 8) * R + r0 + tx] = __float2half_rn(tile[tx][ty + i * 8]);
}

// ---------------------------------------------------------------------------
// Kernel 2b: fp32 -> fp16 copy (node_feat)
// ---------------------------------------------------------------------------
__global__ __launch_bounds__(256) void half_copy_kernel(
    const float4* __restrict__ in, __half2* __restrict__ out)
{
    long i = (long)blockIdx.x * 256 + threadIdx.x;
    float4 v = in[i];
    out[2 * i + 0] = __floats2half2_rn(v.x, v.y);
    out[2 * i + 1] = __floats2half2_rn(v.z, v.w);
}

// ---------------------------------------------------------------------------
// Kernel 3: FUSED INPUT PROJECTION.
//   phase 1: Z = nf[rows,:] @ W_in  (K=512, fp32 acc)
//   phase 2: h = relu(LN(Z + b_in)) ; write h (fp32) + hT (fp16 transposed)
// grid (M_all/128), 512 threads = 16 warps (2m x 8n).
// ---------------------------------------------------------------------------
__global__ __launch_bounds__(512, 1) void proj_fused(
    const __half* __restrict__ A,      // nf [M,512] fp16
    const __half* __restrict__ Bt,     // winT [256][512]
    const float* __restrict__ bias,
    const float* __restrict__ gamma,
    const float* __restrict__ beta,
    float* __restrict__ dstF,          // h
    __half* __restrict__ hTout)        // hT
{
    extern __shared__ char smem[];
    const uint32_t sb = smem_u32(smem);
    const int tid  = threadIdx.x;
    const int wid  = tid >> 5;
    const int lane = tid & 31;
    const int bm   = blockIdx.x * 128;
    const int b    = bm >> 11;         // batch index (bm / NN)

    const int wm = (wid & 1) * 64;
    const int wn = (wid >> 1) * 32;
    const int tr   = lane & 7;
    const int sel  = lane >> 3;
    const int aRow = (sel & 1) * 8;
    const int aKf  = sel >> 1;
    const int bKf  = sel & 1;

    float acc[4][4][4];
#pragma unroll
    for (int a = 0; a < 4; a++)
#pragma unroll
        for (int x = 0; x < 4; x++)
#pragma unroll
            for (int c = 0; c < 4; c++) acc[a][x][c] = 0.f;

    auto load_chunk = [&](int i, int buf) {
        const uint32_t aBase = sb + (uint32_t)buf * 16384u;
        const uint32_t bBase = sb + 49152u + (uint32_t)buf * 32768u;
#pragma unroll
        for (int q = 0; q < 2; q++) {
            int f8 = tid + q * 512;
            int r  = f8 >> 3;
            int cf = f8 & 7;
            cp16(aBase + (uint32_t)(r * 128 + 16 * (cf ^ (r & 7))),
                 A + (long)(bm + r) * FF + i * KC + cf * 8);
        }
#pragma unroll
        for (int q = 0; q < 4; q++) {
            int f8 = tid + q * 512;
            int r  = f8 >> 3;
            int cf = f8 & 7;
            cp16(bBase + (uint32_t)(r * 128 + 16 * (cf ^ (r & 7))),
                 Bt + (long)r * FF + i * KC + cf * 8);
        }
    };

    load_chunk(0, 0); cp_commit();
    load_chunk(1, 1); cp_commit();

    const int nch = FF / KC;   // 8
    int bufc = 0;
    for (int i = 0; i < nch; i++) {
        if (i + 2 < nch) {
            int bufn = bufc + 2; if (bufn >= 3) bufn -= 3;
            load_chunk(i + 2, bufn);
        }
        cp_commit();
        cp_wait<2>();
        __syncthreads();

        const uint32_t aB = sb + (uint32_t)bufc * 16384u;
        const uint32_t bB = sb + 49152u + (uint32_t)bufc * 32768u;
#pragma unroll
        for (int ks = 0; ks < 4; ks++) {
            uint32_t ar[4][4];
#pragma unroll
            for (int mt = 0; mt < 4; mt++) {
                int row = wm + mt * 16 + aRow + tr;
                ldsm_x4(ar[mt], aB + (uint32_t)(row * 128 + 16 * (((ks << 1) + aKf) ^ (row & 7))));
            }
            uint32_t br[4][2];
#pragma unroll
            for (int nt = 0; nt < 4; nt++) {
                int row = wn + nt * 8 + tr;
                ldsm_x2(br[nt], bB + (uint32_t)(row * 128 + 16 * (((ks << 1) + bKf) ^ (row & 7))));
            }
#pragma unroll
            for (int mt = 0; mt < 4; mt++)
#pragma unroll
                for (int nt = 0; nt < 4; nt++)
                    mma_f16(acc[mt][nt], ar[mt], br[nt]);
        }
        __syncthreads();
        bufc++; if (bufc == 3) bufc = 0;
    }

    // ---- LN epilogue (cross-warp) ----
    float* spart = (float*)(smem + SP_OFF);
    float* qpart = (float*)(smem + QP_OFF);
    float* muS   = (float*)(smem + MU_OFF);
    float* rsS   = (float*)(smem + RS_OFF);
    const int wni = wid >> 1;

#pragma unroll
    for (int mt = 0; mt < 4; mt++) {
        float sl = 0.f, ql = 0.f, sh = 0.f, qh = 0.f;
#pragma unroll
        for (int nt = 0; nt < 4; nt++) {
            int c0 = wn + nt * 8 + 2 * (lane & 3);
            float b0 = bias[c0], b1 = bias[c0 + 1];
            float z0 = acc[mt][nt][0] + b0;
            float z1 = acc[mt][nt][1] + b1;
            float z2 = acc[mt][nt][2] + b0;
            float z3 = acc[mt][nt][3] + b1;
            acc[mt][nt][0] = z0; acc[mt][nt][1] = z1;
            acc[mt][nt][2] = z2; acc[mt][nt][3] = z3;
            sl += z0 + z1; ql += z0 * z0 + z1 * z1;
            sh += z2 + z3; qh += z2 * z2 + z3 * z3;
        }
        sl += __shfl_xor_sync(0xffffffffu, sl, 1);
        sl += __shfl_xor_sync(0xffffffffu, sl, 2);
        ql += __shfl_xor_sync(0xffffffffu, ql, 1);
        ql += __shfl_xor_sync(0xffffffffu, ql, 2);
        sh += __shfl_xor_sync(0xffffffffu, sh, 1);
        sh += __shfl_xor_sync(0xffffffffu, sh, 2);
        qh += __shfl_xor_sync(0xffffffffu, qh, 1);
        qh += __shfl_xor_sync(0xffffffffu, qh, 2);
        if ((lane & 3) == 0) {
            int rlo = wm + mt * 16 + (lane >> 2);
            spart[rlo * 8 + wni] = sl;
            qpart[rlo * 8 + wni] = ql;
            spart[(rlo + 8) * 8 + wni] = sh;
            qpart[(rlo + 8) * 8 + wni] = qh;
        }
    }
    __syncthreads();
    if (tid < 128) {
        float s = 0.f, q = 0.f;
#pragma unroll
        for (int j = 0; j < 8; j++) { s += spart[tid * 8 + j]; q += qpart[tid * 8 + j]; }
        float mu  = s * (1.0f / HH);
        float var = q * (1.0f / HH) - mu * mu;
        muS[tid] = mu;
        rsS[tid] = rsqrtf(var + LN_EPS);
    }
    __syncthreads();

    __half* tile = (__half*)smem;
    float* df = dstF + (long)bm * HH;

#pragma unroll
    for (int mt = 0; mt < 4; mt++) {
        int rl = wm + mt * 16 + (lane >> 2);
        int rh = rl + 8;
        float mul = muS[rl], rsl = rsS[rl];
        float muh = muS[rh], rsh = rsS[rh];
#pragma unroll
        for (int nt = 0; nt < 4; nt++) {
            int c0 = wn + nt * 8 + 2 * (lane & 3);
            float g0 = gamma[c0], g1 = gamma[c0 + 1];
            float e0 = beta[c0],  e1 = beta[c0 + 1];
            float y0 = fmaxf((acc[mt][nt][0] - mul) * rsl * g0 + e0, 0.f);
            float y1 = fmaxf((acc[mt][nt][1] - mul) * rsl * g1 + e1, 0.f);
            float y2 = fmaxf((acc[mt][nt][2] - muh) * rsh * g0 + e0, 0.f);
            float y3 = fmaxf((acc[mt][nt][3] - muh) * rsh * g1 + e1, 0.f);
            float2 vlo; vlo.x = y0; vlo.y = y1;
            float2 vhi; vhi.x = y2; vhi.y = y3;
            *(float2*)(df + (long)rl * HH + c0) = vlo;
            *(float2*)(df + (long)rh * HH + c0) = vhi;
            tile[(c0)     * 136 + rl] = __float2half_rn(y0);
            tile[(c0 + 1) * 136 + rl] = __float2half_rn(y1);
            tile[(c0)     * 136 + rh] = __float2half_rn(y2);
            tile[(c0 + 1) * 136 + rh] = __float2half_rn(y3);
        }
    }

    __syncthreads();
    {
        int c  = tid & 255;
        int hs = tid >> 8;
        __half* dst = hTout + ((size_t)b * HH + c) * NN + (bm & (NN - 1)) + hs * 64;
        const uint4* src = (const uint4*)(tile + c * 136 + hs * 64);
#pragma unroll
        for (int g = 0; g < 8; g++)
            ((uint4*)dst)[g] = src[g];
    }
}

// ---------------------------------------------------------------------------
// Kernel 4: FUSED GNN LAYER (as round 7).
// ---------------------------------------------------------------------------
__global__ __launch_bounds__(512, 1) void layer_fused(
    const __half* __restrict__ NA,
    const __half* __restrict__ hTin,
    const __half* __restrict__ Wt,
    const float* __restrict__ bias,
    const float* __restrict__ gamma,
    const float* __restrict__ beta,
    const float* __restrict__ hres,
    float* __restrict__ dstF,
    __half* __restrict__ hTout)
{
    extern __shared__ char smem[];
    const uint32_t sb = smem_u32(smem);
    const int tid  = threadIdx.x;
    const int wid  = tid >> 5;
    const int lane = tid & 31;
    const int bm   = blockIdx.x * 128;
    const int b    = blockIdx.y;

    const __half* A  = NA   + (size_t)b * NN * NN;
    const __half* Bt = hTin + (size_t)b * HH * NN;

    const int wm = (wid & 1) * 64;
    const int wn = (wid >> 1) * 32;
    const int tr   = lane & 7;
    const int sel  = lane >> 3;
    const int aRow = (sel & 1) * 8;
    const int aKf  = sel >> 1;
    const int bKf  = sel & 1;

    float acc[4][4][4];
#pragma unroll
    for (int a = 0; a < 4; a++)
#pragma unroll
        for (int x = 0; x < 4; x++)
#pragma unroll
            for (int c = 0; c < 4; c++) acc[a][x][c] = 0.f;

    // phase 1: K=2048
    auto load_chunk = [&](int i, int buf) {
        const uint32_t aBase = sb + (uint32_t)buf * 16384u;
        const uint32_t bBase = sb + 49152u + (uint32_t)buf * 32768u;
#pragma unroll
        for (int q = 0; q < 2; q++) {
            int f8 = tid + q * 512;
            int r  = f8 >> 3;
            int cf = f8 & 7;
            cp16(aBase + (uint32_t)(r * 128 + 16 * (cf ^ (r & 7))),
                 A + (long)(bm + r) * NN + i * KC + cf * 8);
        }
#pragma unroll
        for (int q = 0; q < 4; q++) {
            int f8 = tid + q * 512;
            int r  = f8 >> 3;
            int cf = f8 & 7;
            cp16(bBase + (uint32_t)(r * 128 + 16 * (cf ^ (r & 7))),
                 Bt + (long)r * NN + i * KC + cf * 8);
        }
    };

    load_chunk(0, 0); cp_commit();
    load_chunk(1, 1); cp_commit();

    const int nch = NN / KC;   // 32
    int bufc = 0;
    for (int i = 0; i < nch; i++) {
        if (i + 2 < nch) {
            int bufn = bufc + 2; if (bufn >= 3) bufn -= 3;
            load_chunk(i + 2, bufn);
        }
        cp_commit();
        cp_wait<2>();
        __syncthreads();

        const uint32_t aB = sb + (uint32_t)bufc * 16384u;
        const uint32_t bB = sb + 49152u + (uint32_t)bufc * 32768u;
#pragma unroll
        for (int ks = 0; ks < 4; ks++) {
            uint32_t ar[4][4];
#pragma unroll
            for (int mt = 0; mt < 4; mt++) {
                int row = wm + mt * 16 + aRow + tr;
                ldsm_x4(ar[mt], aB + (uint32_t)(row * 128 + 16 * (((ks << 1) + aKf) ^ (row & 7))));
            }
            uint32_t br[4][2];
#pragma unroll
            for (int nt = 0; nt < 4; nt++) {
                int row = wn + nt * 8 + tr;
                ldsm_x2(br[nt], bB + (uint32_t)(row * 128 + 16 * (((ks << 1) + bKf) ^ (row & 7))));
            }
#pragma unroll
            for (int mt = 0; mt < 4; mt++)
#pragma unroll
                for (int nt = 0; nt < 4; nt++)
                    mma_f16(acc[mt][nt], ar[mt], br[nt]);
        }
        __syncthreads();
        bufc++; if (bufc == 3) bufc = 0;
    }

    // phase 2 staging
#pragma unroll
    for (int q = 0; q < 16; q++) {
        int u     = tid + q * 512;
        int chunk = u >> 11;
        int v     = u & 2047;
        int r     = v >> 3;
        int cf    = v & 7;
        cp16(sb + (uint32_t)(chunk * 32768 + r * 128 + 16 * (cf ^ (r & 7))),
             Wt + (long)r * 256 + chunk * 64 + cf * 8);
    }
    cp_commit();

    {
        const uint32_t a2base = sb + A2_OFF + (uint32_t)(wn >> 6) * 16384u;
        const int ubase = (wn & 32) >> 3;
        const uint32_t coff = (uint32_t)(4 * (lane & 3));
#pragma unroll
        for (int mt = 0; mt < 4; mt++) {
            int rlo = wm + mt * 16 + (lane >> 2);
            int rhi = rlo + 8;
#pragma unroll
            for (int nt = 0; nt < 4; nt++) {
                int u = ubase + nt;
                uint32_t alo = a2base + (uint32_t)(rlo * 128 + 16 * (u ^ (rlo & 7))) + coff;
                uint32_t ahi = a2base + (uint32_t)(rhi * 128 + 16 * (u ^ (rhi & 7))) + coff;
                *(__half2*)(smem + (alo - sb)) = __floats2half2_rn(acc[mt][nt][0], acc[mt][nt][1]);
                *(__half2*)(smem + (ahi - sb)) = __floats2half2_rn(acc[mt][nt][2], acc[mt][nt][3]);
            }
        }
    }
    cp_wait<0>();
    __syncthreads();

    // phase 2 mainloop
    float acc2[4][4][4];
#pragma unroll
    for (int a = 0; a < 4; a++)
#pragma unroll
        for (int x = 0; x < 4; x++)
#pragma unroll
            for (int c = 0; c < 4; c++) acc2[a][x][c] = 0.f;

#pragma unroll
    for (int i = 0; i < 4; i++) {
        const uint32_t aB = sb + A2_OFF + (uint32_t)i * 16384u;
        const uint32_t bB = sb + (uint32_t)i * 32768u;
#pragma unroll
        for (int ks = 0; ks < 4; ks++) {
            uint32_t ar[4][4];
#pragma unroll
            for (int mt = 0; mt < 4; mt++) {
                int row = wm + mt * 16 + aRow + tr;
                ldsm_x4(ar[mt], aB + (uint32_t)(row * 128 + 16 * (((ks << 1) + aKf) ^ (row & 7))));
            }
            uint32_t br[4][2];
#pragma unroll
            for (int nt = 0; nt < 4; nt++) {
                int row = wn + nt * 8 + tr;
                ldsm_x2(br[nt], bB + (uint32_t)(row * 128 + 16 * (((ks << 1) + bKf) ^ (row & 7))));
            }
#pragma unroll
            for (int mt = 0; mt < 4; mt++)
#pragma unroll
                for (int nt = 0; nt < 4; nt++)
                    mma_f16(acc2[mt][nt], ar[mt], br[nt]);
        }
    }
    __syncthreads();

    // phase 3: LN epilogue
    float* spart = (float*)(smem + SP_OFF);
    float* qpart = (float*)(smem + QP_OFF);
    float* muS   = (float*)(smem + MU_OFF);
    float* rsS   = (float*)(smem + RS_OFF);
    const int wni = wid >> 1;

#pragma unroll
    for (int mt = 0; mt < 4; mt++) {
        float sl = 0.f, ql = 0.f, sh = 0.f, qh = 0.f;
#pragma unroll
        for (int nt = 0; nt < 4; nt++) {
            int c0 = wn + nt * 8 + 2 * (lane & 3);
            float b0 = bias[c0], b1 = bias[c0 + 1];
            float z0 = acc2[mt][nt][0] + b0;
            float z1 = acc2[mt][nt][1] + b1;
            float z2 = acc2[mt][nt][2] + b0;
            float z3 = acc2[mt][nt][3] + b1;
            acc2[mt][nt][0] = z0; acc2[mt][nt][1] = z1;
            acc2[mt][nt][2] = z2; acc2[mt][nt][3] = z3;
            sl += z0 + z1; ql += z0 * z0 + z1 * z1;
            sh += z2 + z3; qh += z2 * z2 + z3 * z3;
        }
        sl += __shfl_xor_sync(0xffffffffu, sl, 1);
        sl += __shfl_xor_sync(0xffffffffu, sl, 2);
        ql += __shfl_xor_sync(0xffffffffu, ql, 1);
        ql += __shfl_xor_sync(0xffffffffu, ql, 2);
        sh += __shfl_xor_sync(0xffffffffu, sh, 1);
        sh += __shfl_xor_sync(0xffffffffu, sh, 2);
        qh += __shfl_xor_sync(0xffffffffu, qh, 1);
        qh += __shfl_xor_sync(0xffffffffu, qh, 2);
        if ((lane & 3) == 0) {
            int rlo = wm + mt * 16 + (lane >> 2);
            spart[rlo * 8 + wni] = sl;
            qpart[rlo * 8 + wni] = ql;
            spart[(rlo + 8) * 8 + wni] = sh;
            qpart[(rlo + 8) * 8 + wni] = qh;
        }
    }
    __syncthreads();
    if (tid < 128) {
        float s = 0.f, q = 0.f;
#pragma unroll
        for (int j = 0; j < 8; j++) { s += spart[tid * 8 + j]; q += qpart[tid * 8 + j]; }
        float mu  = s * (1.0f / HH);
        float var = q * (1.0f / HH) - mu * mu;
        muS[tid] = mu;
        rsS[tid] = rsqrtf(var + LN_EPS);
    }
    __syncthreads();

    __half* tile = (__half*)smem;
    const bool doT = (hTout != nullptr);
    const float* hr = hres + ((size_t)b * NN + bm) * HH;
    float* df       = dstF + ((size_t)b * NN + bm) * HH;

#pragma unroll
    for (int mt = 0; mt < 4; mt++) {
        int rl = wm + mt * 16 + (lane >> 2);
        int rh = rl + 8;
        float mul = muS[rl], rsl = rsS[rl];
        float muh = muS[rh], rsh = rsS[rh];
#pragma unroll
        for (int nt = 0; nt < 4; nt++) {
            int c0 = wn + nt * 8 + 2 * (lane & 3);
            float g0 = gamma[c0], g1 = gamma[c0 + 1];
            float e0 = beta[c0],  e1 = beta[c0 + 1];
            float y0 = fmaxf((acc2[mt][nt][0] - mul) * rsl * g0 + e0, 0.f) + hr[(long)rl * HH + c0];
            float y1 = fmaxf((acc2[mt][nt][1] - mul) * rsl * g1 + e1, 0.f) + hr[(long)rl * HH + c0 + 1];
            float y2 = fmaxf((acc2[mt][nt][2] - muh) * rsh * g0 + e0, 0.f) + hr[(long)rh * HH + c0];
            float y3 = fmaxf((acc2[mt][nt][3] - muh) * rsh * g1 + e1, 0.f) + hr[(long)rh * HH + c0 + 1];
            float2 vlo; vlo.x = y0; vlo.y = y1;
            float2 vhi; vhi.x = y2; vhi.y = y3;
            *(float2*)(df + (long)rl * HH + c0) = vlo;
            *(float2*)(df + (long)rh * HH + c0) = vhi;
            if (doT) {
                tile[(c0)     * 136 + rl] = __float2half_rn(y0);
                tile[(c0 + 1) * 136 + rl] = __float2half_rn(y1);
                tile[(c0)     * 136 + rh] = __float2half_rn(y2);
                tile[(c0 + 1) * 136 + rh] = __float2half_rn(y3);
            }
        }
    }

    if (doT) {
        __syncthreads();
        int c  = tid & 255;
        int hs = tid >> 8;
        __half* dst = hTout + ((size_t)b * HH + c) * NN + bm + hs * 64;
        const uint4* src = (const uint4*)(tile + c * 136 + hs * 64);
#pragma unroll
        for (int g = 0; g < 8; g++)
            ((uint4*)dst)[g] = src[g];
    }
}

// ---------------------------------------------------------------------------
// Launch orchestration (graph-capturable)
// ---------------------------------------------------------------------------
extern "C" void kernel_launch(void* const* d_in, const int* in_sizes, int n_in,
                              void* d_out, int out_size)
{
    const float* node_feat = (const float*)d_in[0];
    const float* edge_w    = (const float*)d_in[1];
    const float* adj       = (const float*)d_in[2];
    const float* W_in      = (const float*)d_in[3];
    const float* b_in      = (const float*)d_in[4];
    const float* g_in      = (const float*)d_in[5];
    const float* bt_in     = (const float*)d_in[6];
    const float* W         = (const float*)d_in[7];
    const float* bvec      = (const float*)d_in[8];
    const float* gamma     = (const float*)d_in[9];
    const float* beta      = (const float*)d_in[10];
    float* out = (float*)d_out;

    __half *na_p, *nf_p, *hTa_p, *hTb_p, *wT_p;
    float *h_p;
    cudaGetSymbolAddress((void**)&na_p,  g_norm_adj);
    cudaGetSymbolAddress((void**)&nf_p,  g_nf);
    cudaGetSymbolAddress((void**)&h_p,   g_h);
    cudaGetSymbolAddress((void**)&hTa_p, g_hTa);
    cudaGetSymbolAddress((void**)&hTb_p, g_hTb);
    cudaGetSymbolAddress((void**)&wT_p,  g_wT);

    cudaFuncSetAttribute(proj_fused,  cudaFuncAttributeMaxDynamicSharedMemorySize, FUSED_SMEM);
    cudaFuncSetAttribute(layer_fused, cudaFuncAttributeMaxDynamicSharedMemorySize, FUSED_SMEM);

    const int M_all = BB * NN;
    __half* winT = wT_p;
    __half* wlT  = wT_p + 256 * 512;

    // 1. normalized adjacency -> fp16
    norm_adj_kernel<<<dim3(NN, BB), 256>>>(
        (const float4*)adj, (const float4*)edge_w, na_p);

    // 2. weight transposes -> fp16
    transpose_kernel<<<dim3(HH / 32, FF / 32, 1), dim3(32, 8)>>>(
        W_in, winT, FF, HH, 0, 0);
    transpose_kernel<<<dim3(HH / 32, HH / 32, LL), dim3(32, 8)>>>(
        W, wlT, HH, HH, (long)HH * HH, (long)HH * HH);

    // 3. node_feat -> fp16
    half_copy_kernel<<<(int)(((long)M_all * FF / 4) / 256), 256>>>(
        (const float4*)node_feat, (__half2*)nf_p);

    // 4. fused input projection + LN -> h + hT_a
    proj_fused<<<dim3(M_all / 128, 1), 512, FUSED_SMEM>>>(
        nf_p, winT, b_in, g_in, bt_in, h_p, hTa_p);

    // 5. fused GNN layers with hT ping-pong
    __half* hT_cur = hTa_p;
    __half* hT_nxt = hTb_p;
    for (int l = 0; l < LL; l++) {
        const bool last = (l == LL - 1);
        layer_fused<<<dim3(NN / 128, BB), 512, FUSED_SMEM>>>(
            na_p, hT_cur, wlT + (long)l * HH * HH,
            bvec + (long)l * HH, gamma + (long)l * HH, beta + (long)l * HH,
            h_p,
            last ? out : h_p,
            last ? nullptr : hT_nxt);
        __half* t = hT_cur; hT_cur = hT_nxt; hT_nxt = t;
    }
}

// round 9
// speedup vs baseline: 5.8823x; 1.0154x over previous
#include <cuda_runtime.h>
#include <cuda_fp16.h>
#include <math.h>
#include <stdint.h>

// Problem constants
#define BB 8
#define NN 2048
#define FF 512
#define HH 256
#define LL 3
#define LN_EPS 1e-5f

// ---------------------------------------------------------------------------
// Device scratch (static — no cudaMalloc allowed)
// ---------------------------------------------------------------------------
__device__ __align__(128) __half g_norm_adj[(size_t)BB * NN * NN];   // 67 MB
__device__ __align__(128) __half g_nf[(size_t)BB * NN * FF];         // 16.8 MB
__device__ __align__(128) float  g_h[(size_t)BB * NN * HH];          // fp32 residual
__device__ __align__(128) __half g_hTa[(size_t)BB * HH * NN];        // hT ping
__device__ __align__(128) __half g_hTb[(size_t)BB * HH * NN];        // hT pong
__device__ __align__(128) __half g_wT[256 * 512 + 3 * 256 * 256];    // W_in^T, W[l]^T

// ---------------------------------------------------------------------------
// Helpers
// ---------------------------------------------------------------------------
__device__ __forceinline__ uint32_t smem_u32(const void* p) {
    uint32_t a;
    asm("{ .reg .u64 t; cvta.to.shared.u64 t, %1; cvt.u32.u64 %0, t; }" : "=r"(a) : "l"(p));
    return a;
}
__device__ __forceinline__ void cp16(uint32_t dst, const void* src) {
    asm volatile("cp.async.cg.shared.global [%0], [%1], 16;" :: "r"(dst), "l"(src) : "memory");
}
__device__ __forceinline__ void cp_commit() {
    asm volatile("cp.async.commit_group;" ::: "memory");
}
template <int N> __device__ __forceinline__ void cp_wait() {
    asm volatile("cp.async.wait_group %0;" :: "n"(N) : "memory");
}
__device__ __forceinline__ void ldsm_x4(uint32_t* r, uint32_t addr) {
    asm volatile("ldmatrix.sync.aligned.m8n8.x4.shared.b16 {%0,%1,%2,%3}, [%4];"
                 : "=r"(r[0]), "=r"(r[1]), "=r"(r[2]), "=r"(r[3]) : "r"(addr));
}
__device__ __forceinline__ void ldsm_x2(uint32_t* r, uint32_t addr) {
    asm volatile("ldmatrix.sync.aligned.m8n8.x2.shared.b16 {%0,%1}, [%2];"
                 : "=r"(r[0]), "=r"(r[1]) : "r"(addr));
}
__device__ __forceinline__ void mma_f16(float* c, const uint32_t* a, const uint32_t* b) {
    asm volatile("mma.sync.aligned.m16n8k16.row.col.f32.f16.f16.f32 "
                 "{%0,%1,%2,%3}, {%4,%5,%6,%7}, {%8,%9}, {%0,%1,%2,%3};"
                 : "+f"(c[0]), "+f"(c[1]), "+f"(c[2]), "+f"(c[3])
                 : "r"(a[0]), "r"(a[1]), "r"(a[2]), "r"(a[3]), "r"(b[0]), "r"(b[1]));
}

// smem region offsets for fused kernels
#define KC 64
#define A2_OFF    147456u
#define SP_OFF    (A2_OFF + 65536u)
#define QP_OFF    (SP_OFF + 4096u)
#define MU_OFF    (QP_OFF + 4096u)
#define RS_OFF    (MU_OFF + 512u)
#define FUSED_SMEM (RS_OFF + 512u)

// ---------------------------------------------------------------------------
// Kernel 1: normalized adjacency -> fp16
// ---------------------------------------------------------------------------
__global__ __launch_bounds__(256) void norm_adj_kernel(
    const float4* __restrict__ adj, const float4* __restrict__ ew,
    __half* __restrict__ out)
{
    const int row = blockIdx.x;
    const int b   = blockIdx.y;
    const long base4 = ((long)b * NN + row) * (NN / 4);
    const float4* __restrict__ arow = adj + base4;
    const float4* __restrict__ erow = ew + base4;
    __half2* __restrict__ orow = (__half2*)(out + ((long)b * NN + row) * NN);

    __shared__ float4 w4[NN / 4];
    __shared__ float sbuf[8];

    const int diag4 = row >> 2;
    const int diagc = row & 3;

    float lsum = 0.f;
#pragma unroll
    for (int i = 0; i < 2; i++) {
        int c4 = threadIdx.x + i * 256;
        float4 a = arow[c4];
        float4 e = erow[c4];
        if (c4 == diag4) {
            if (diagc == 0) a.x += 1.f;
            else if (diagc == 1) a.y += 1.f;
            else if (diagc == 2) a.z += 1.f;
            else a.w += 1.f;
        }
        float4 v;
        v.x = fminf(a.x, 1.f) * e.x;
        v.y = fminf(a.y, 1.f) * e.y;
        v.z = fminf(a.z, 1.f) * e.z;
        v.w = fminf(a.w, 1.f) * e.w;
        w4[c4] = v;
        lsum += v.x + v.y + v.z + v.w;
    }
#pragma unroll
    for (int o = 16; o > 0; o >>= 1) lsum += __shfl_down_sync(0xffffffffu, lsum, o);
    int lane = threadIdx.x & 31, wid = threadIdx.x >> 5;
    if (lane == 0) sbuf[wid] = lsum;
    __syncthreads();
    if (wid == 0) {
        float v = (lane < 8) ? sbuf[lane] : 0.f;
#pragma unroll
        for (int o = 4; o > 0; o >>= 1) v += __shfl_down_sync(0xffffffffu, v, o);
        if (lane == 0) sbuf[0] = v;
    }
    __syncthreads();
    const float inv = 1.0f / (sbuf[0] + 1e-8f);

#pragma unroll
    for (int i = 0; i < 2; i++) {
        int c4 = threadIdx.x + i * 256;
        float4 v = w4[c4];
        orow[2 * c4 + 0] = __floats2half2_rn(v.x * inv, v.y * inv);
        orow[2 * c4 + 1] = __floats2half2_rn(v.z * inv, v.w * inv);
    }
}

// ---------------------------------------------------------------------------
// Kernel 2: 32x32 transpose, fp32 -> fp16 (weights)
// ---------------------------------------------------------------------------
__global__ __launch_bounds__(256) void transpose_kernel(
    const float* __restrict__ in, __half* __restrict__ out,
    int R, int C, long sIn, long sOut)
{
    __shared__ float tile[32][33];
    const int bz = blockIdx.z;
    in  += (long)bz * sIn;
    out += (long)bz * sOut;
    const int c0 = blockIdx.x * 32;
    const int r0 = blockIdx.y * 32;
    const int tx = threadIdx.x, ty = threadIdx.y;
#pragma unroll
    for (int i = 0; i < 4; i++)
        tile[ty + i * 8][tx] = in[(long)(r0 + ty + i * 8) * C + c0 + tx];
    __syncthreads();
#pragma unroll
    for (int i = 0; i < 4; i++)
        out[(long)(c0 + ty + i * 8) * R + r0 + tx] = __float2half_rn(tile[tx][ty + i * 8]);
}

// ---------------------------------------------------------------------------
// Kernel 2b: fp32 -> fp16 copy (node_feat)
// ---------------------------------------------------------------------------
__global__ __launch_bounds__(256) void half_copy_kernel(
    const float4* __restrict__ in, __half2* __restrict__ out)
{
    long i = (long)blockIdx.x * 256 + threadIdx.x;
    float4 v = in[i];
    out[2 * i + 0] = __floats2half2_rn(v.x, v.y);
    out[2 * i + 1] = __floats2half2_rn(v.z, v.w);
}

// ---------------------------------------------------------------------------
// Kernel 3: FUSED INPUT PROJECTION (GEMM K=512 + LN epilogue)
// ---------------------------------------------------------------------------
__global__ __launch_bounds__(512, 1) void proj_fused(
    const __half* __restrict__ A,
    const __half* __restrict__ Bt,
    const float* __restrict__ bias,
    const float* __restrict__ gamma,
    const float* __restrict__ beta,
    float* __restrict__ dstF,
    __half* __restrict__ hTout)
{
    extern __shared__ char smem[];
    const uint32_t sb = smem_u32(smem);
    const int tid  = threadIdx.x;
    const int wid  = tid >> 5;
    const int lane = tid & 31;
    const int bm   = blockIdx.x * 128;
    const int b    = bm >> 11;

    const int wm = (wid & 1) * 64;
    const int wn = (wid >> 1) * 32;
    const int tr   = lane & 7;
    const int sel  = lane >> 3;
    const int aRow = (sel & 1) * 8;
    const int aKf  = sel >> 1;
    const int bKf  = sel & 1;

    float acc[4][4][4];
#pragma unroll
    for (int a = 0; a < 4; a++)
#pragma unroll
        for (int x = 0; x < 4; x++)
#pragma unroll
            for (int c = 0; c < 4; c++) acc[a][x][c] = 0.f;

    auto load_chunk = [&](int i, int buf) {
        const uint32_t aBase = sb + (uint32_t)buf * 16384u;
        const uint32_t bBase = sb + 49152u + (uint32_t)buf * 32768u;
#pragma unroll
        for (int q = 0; q < 2; q++) {
            int f8 = tid + q * 512;
            int r  = f8 >> 3;
            int cf = f8 & 7;
            cp16(aBase + (uint32_t)(r * 128 + 16 * (cf ^ (r & 7))),
                 A + (long)(bm + r) * FF + i * KC + cf * 8);
        }
#pragma unroll
        for (int q = 0; q < 4; q++) {
            int f8 = tid + q * 512;
            int r  = f8 >> 3;
            int cf = f8 & 7;
            cp16(bBase + (uint32_t)(r * 128 + 16 * (cf ^ (r & 7))),
                 Bt + (long)r * FF + i * KC + cf * 8);
        }
    };

    load_chunk(0, 0); cp_commit();
    load_chunk(1, 1); cp_commit();

    const int nch = FF / KC;   // 8
    int bufc = 0;
    for (int i = 0; i < nch; i++) {
        if (i + 1 < nch) cp_wait<1>(); else cp_wait<0>();
        __syncthreads();
        if (i + 2 < nch) {
            int bufn = bufc + 2; if (bufn >= 3) bufn -= 3;
            load_chunk(i + 2, bufn);
            cp_commit();
        }

        const uint32_t aB = sb + (uint32_t)bufc * 16384u;
        const uint32_t bB = sb + 49152u + (uint32_t)bufc * 32768u;
#pragma unroll
        for (int ks = 0; ks < 4; ks++) {
            uint32_t ar[4][4];
#pragma unroll
            for (int mt = 0; mt < 4; mt++) {
                int row = wm + mt * 16 + aRow + tr;
                ldsm_x4(ar[mt], aB + (uint32_t)(row * 128 + 16 * (((ks << 1) + aKf) ^ (row & 7))));
            }
            uint32_t br[4][2];
#pragma unroll
            for (int nt = 0; nt < 4; nt++) {
                int row = wn + nt * 8 + tr;
                ldsm_x2(br[nt], bB + (uint32_t)(row * 128 + 16 * (((ks << 1) + bKf) ^ (row & 7))));
            }
#pragma unroll
            for (int mt = 0; mt < 4; mt++)
#pragma unroll
                for (int nt = 0; nt < 4; nt++)
                    mma_f16(acc[mt][nt], ar[mt], br[nt]);
        }
        bufc++; if (bufc == 3) bufc = 0;
    }

    // LN epilogue
    float* spart = (float*)(smem + SP_OFF);
    float* qpart = (float*)(smem + QP_OFF);
    float* muS   = (float*)(smem + MU_OFF);
    float* rsS   = (float*)(smem + RS_OFF);
    const int wni = wid >> 1;

#pragma unroll
    for (int mt = 0; mt < 4; mt++) {
        float sl = 0.f, ql = 0.f, sh = 0.f, qh = 0.f;
#pragma unroll
        for (int nt = 0; nt < 4; nt++) {
            int c0 = wn + nt * 8 + 2 * (lane & 3);
            float b0 = bias[c0], b1 = bias[c0 + 1];
            float z0 = acc[mt][nt][0] + b0;
            float z1 = acc[mt][nt][1] + b1;
            float z2 = acc[mt][nt][2] + b0;
            float z3 = acc[mt][nt][3] + b1;
            acc[mt][nt][0] = z0; acc[mt][nt][1] = z1;
            acc[mt][nt][2] = z2; acc[mt][nt][3] = z3;
            sl += z0 + z1; ql += z0 * z0 + z1 * z1;
            sh += z2 + z3; qh += z2 * z2 + z3 * z3;
        }
        sl += __shfl_xor_sync(0xffffffffu, sl, 1);
        sl += __shfl_xor_sync(0xffffffffu, sl, 2);
        ql += __shfl_xor_sync(0xffffffffu, ql, 1);
        ql += __shfl_xor_sync(0xffffffffu, ql, 2);
        sh += __shfl_xor_sync(0xffffffffu, sh, 1);
        sh += __shfl_xor_sync(0xffffffffu, sh, 2);
        qh += __shfl_xor_sync(0xffffffffu, qh, 1);
        qh += __shfl_xor_sync(0xffffffffu, qh, 2);
        if ((lane & 3) == 0) {
            int rlo = wm + mt * 16 + (lane >> 2);
            spart[rlo * 8 + wni] = sl;
            qpart[rlo * 8 + wni] = ql;
            spart[(rlo + 8) * 8 + wni] = sh;
            qpart[(rlo + 8) * 8 + wni] = qh;
        }
    }
    __syncthreads();
    if (tid < 128) {
        float s = 0.f, q = 0.f;
#pragma unroll
        for (int j = 0; j < 8; j++) { s += spart[tid * 8 + j]; q += qpart[tid * 8 + j]; }
        float mu  = s * (1.0f / HH);
        float var = q * (1.0f / HH) - mu * mu;
        muS[tid] = mu;
        rsS[tid] = rsqrtf(var + LN_EPS);
    }
    __syncthreads();

    __half* tile = (__half*)smem;
    float* df = dstF + (long)bm * HH;

#pragma unroll
    for (int mt = 0; mt < 4; mt++) {
        int rl = wm + mt * 16 + (lane >> 2);
        int rh = rl + 8;
        float mul = muS[rl], rsl = rsS[rl];
        float muh = muS[rh], rsh = rsS[rh];
#pragma unroll
        for (int nt = 0; nt < 4; nt++) {
            int c0 = wn + nt * 8 + 2 * (lane & 3);
            float g0 = gamma[c0], g1 = gamma[c0 + 1];
            float e0 = beta[c0],  e1 = beta[c0 + 1];
            float y0 = fmaxf((acc[mt][nt][0] - mul) * rsl * g0 + e0, 0.f);
            float y1 = fmaxf((acc[mt][nt][1] - mul) * rsl * g1 + e1, 0.f);
            float y2 = fmaxf((acc[mt][nt][2] - muh) * rsh * g0 + e0, 0.f);
            float y3 = fmaxf((acc[mt][nt][3] - muh) * rsh * g1 + e1, 0.f);
            float2 vlo; vlo.x = y0; vlo.y = y1;
            float2 vhi; vhi.x = y2; vhi.y = y3;
            *(float2*)(df + (long)rl * HH + c0) = vlo;
            *(float2*)(df + (long)rh * HH + c0) = vhi;
            tile[(c0)     * 136 + rl] = __float2half_rn(y0);
            tile[(c0 + 1) * 136 + rl] = __float2half_rn(y1);
            tile[(c0)     * 136 + rh] = __float2half_rn(y2);
            tile[(c0 + 1) * 136 + rh] = __float2half_rn(y3);
        }
    }

    __syncthreads();
    {
        int c  = tid & 255;
        int hs = tid >> 8;
        __half* dst = hTout + ((size_t)b * HH + c) * NN + (bm & (NN - 1)) + hs * 64;
        const uint4* src = (const uint4*)(tile + c * 136 + hs * 64);
#pragma unroll
        for (int g = 0; g < 8; g++)
            ((uint4*)dst)[g] = src[g];
    }
}

// ---------------------------------------------------------------------------
// Kernel 4: FUSED GNN LAYER (single sync/chunk mainloop)
// ---------------------------------------------------------------------------
__global__ __launch_bounds__(512, 1) void layer_fused(
    const __half* __restrict__ NA,
    const __half* __restrict__ hTin,
    const __half* __restrict__ Wt,
    const float* __restrict__ bias,
    const float* __restrict__ gamma,
    const float* __restrict__ beta,
    const float* __restrict__ hres,
    float* __restrict__ dstF,
    __half* __restrict__ hTout)
{
    extern __shared__ char smem[];
    const uint32_t sb = smem_u32(smem);
    const int tid  = threadIdx.x;
    const int wid  = tid >> 5;
    const int lane = tid & 31;
    const int bm   = blockIdx.x * 128;
    const int b    = blockIdx.y;

    const __half* A  = NA   + (size_t)b * NN * NN;
    const __half* Bt = hTin + (size_t)b * HH * NN;

    const int wm = (wid & 1) * 64;
    const int wn = (wid >> 1) * 32;
    const int tr   = lane & 7;
    const int sel  = lane >> 3;
    const int aRow = (sel & 1) * 8;
    const int aKf  = sel >> 1;
    const int bKf  = sel & 1;

    float acc[4][4][4];
#pragma unroll
    for (int a = 0; a < 4; a++)
#pragma unroll
        for (int x = 0; x < 4; x++)
#pragma unroll
            for (int c = 0; c < 4; c++) acc[a][x][c] = 0.f;

    auto load_chunk = [&](int i, int buf) {
        const uint32_t aBase = sb + (uint32_t)buf * 16384u;
        const uint32_t bBase = sb + 49152u + (uint32_t)buf * 32768u;
#pragma unroll
        for (int q = 0; q < 2; q++) {
            int f8 = tid + q * 512;
            int r  = f8 >> 3;
            int cf = f8 & 7;
            cp16(aBase + (uint32_t)(r * 128 + 16 * (cf ^ (r & 7))),
                 A + (long)(bm + r) * NN + i * KC + cf * 8);
        }
#pragma unroll
        for (int q = 0; q < 4; q++) {
            int f8 = tid + q * 512;
            int r  = f8 >> 3;
            int cf = f8 & 7;
            cp16(bBase + (uint32_t)(r * 128 + 16 * (cf ^ (r & 7))),
                 Bt + (long)r * NN + i * KC + cf * 8);
        }
    };

    load_chunk(0, 0); cp_commit();
    load_chunk(1, 1); cp_commit();

    const int nch = NN / KC;   // 32
    int bufc = 0;
    for (int i = 0; i < nch; i++) {
        if (i + 1 < nch) cp_wait<1>(); else cp_wait<0>();
        __syncthreads();
        if (i + 2 < nch) {
            int bufn = bufc + 2; if (bufn >= 3) bufn -= 3;
            load_chunk(i + 2, bufn);
            cp_commit();
        }

        const uint32_t aB = sb + (uint32_t)bufc * 16384u;
        const uint32_t bB = sb + 49152u + (uint32_t)bufc * 32768u;
#pragma unroll
        for (int ks = 0; ks < 4; ks++) {
            uint32_t ar[4][4];
#pragma unroll
            for (int mt = 0; mt < 4; mt++) {
                int row = wm + mt * 16 + aRow + tr;
                ldsm_x4(ar[mt], aB + (uint32_t)(row * 128 + 16 * (((ks << 1) + aKf) ^ (row & 7))));
            }
            uint32_t br[4][2];
#pragma unroll
            for (int nt = 0; nt < 4; nt++) {
                int row = wn + nt * 8 + tr;
                ldsm_x2(br[nt], bB + (uint32_t)(row * 128 + 16 * (((ks << 1) + bKf) ^ (row & 7))));
            }
#pragma unroll
            for (int mt = 0; mt < 4; mt++)
#pragma unroll
                for (int nt = 0; nt < 4; nt++)
                    mma_f16(acc[mt][nt], ar[mt], br[nt]);
        }
        bufc++; if (bufc == 3) bufc = 0;
    }
    __syncthreads();   // fence phase-1 smem reads before phase-2 overwrites

    // phase 2 staging
#pragma unroll
    for (int q = 0; q < 16; q++) {
        int u     = tid + q * 512;
        int chunk = u >> 11;
        int v     = u & 2047;
        int r     = v >> 3;
        int cf    = v & 7;
        cp16(sb + (uint32_t)(chunk * 32768 + r * 128 + 16 * (cf ^ (r & 7))),
             Wt + (long)r * 256 + chunk * 64 + cf * 8);
    }
    cp_commit();

    {
        const uint32_t a2base = sb + A2_OFF + (uint32_t)(wn >> 6) * 16384u;
        const int ubase = (wn & 32) >> 3;
        const uint32_t coff = (uint32_t)(4 * (lane & 3));
#pragma unroll
        for (int mt = 0; mt < 4; mt++) {
            int rlo = wm + mt * 16 + (lane >> 2);
            int rhi = rlo + 8;
#pragma unroll
            for (int nt = 0; nt < 4; nt++) {
                int u = ubase + nt;
                uint32_t alo = a2base + (uint32_t)(rlo * 128 + 16 * (u ^ (rlo & 7))) + coff;
                uint32_t ahi = a2base + (uint32_t)(rhi * 128 + 16 * (u ^ (rhi & 7))) + coff;
                *(__half2*)(smem + (alo - sb)) = __floats2half2_rn(acc[mt][nt][0], acc[mt][nt][1]);
                *(__half2*)(smem + (ahi - sb)) = __floats2half2_rn(acc[mt][nt][2], acc[mt][nt][3]);
            }
        }
    }
    cp_wait<0>();
    __syncthreads();

    // phase 2 mainloop (4 resident chunks, K=256)
    float acc2[4][4][4];
#pragma unroll
    for (int a = 0; a < 4; a++)
#pragma unroll
        for (int x = 0; x < 4; x++)
#pragma unroll
            for (int c = 0; c < 4; c++) acc2[a][x][c] = 0.f;

#pragma unroll
    for (int i = 0; i < 4; i++) {
        const uint32_t aB = sb + A2_OFF + (uint32_t)i * 16384u;
        const uint32_t bB = sb + (uint32_t)i * 32768u;
#pragma unroll
        for (int ks = 0; ks < 4; ks++) {
            uint32_t ar[4][4];
#pragma unroll
            for (int mt = 0; mt < 4; mt++) {
                int row = wm + mt * 16 + aRow + tr;
                ldsm_x4(ar[mt], aB + (uint32_t)(row * 128 + 16 * (((ks << 1) + aKf) ^ (row & 7))));
            }
            uint32_t br[4][2];
#pragma unroll
            for (int nt = 0; nt < 4; nt++) {
                int row = wn + nt * 8 + tr;
                ldsm_x2(br[nt], bB + (uint32_t)(row * 128 + 16 * (((ks << 1) + bKf) ^ (row & 7))));
            }
#pragma unroll
            for (int mt = 0; mt < 4; mt++)
#pragma unroll
                for (int nt = 0; nt < 4; nt++)
                    mma_f16(acc2[mt][nt], ar[mt], br[nt]);
        }
    }
    __syncthreads();

    // phase 3: LN epilogue
    float* spart = (float*)(smem + SP_OFF);
    float* qpart = (float*)(smem + QP_OFF);
    float* muS   = (float*)(smem + MU_OFF);
    float* rsS   = (float*)(smem + RS_OFF);
    const int wni = wid >> 1;

#pragma unroll
    for (int mt = 0; mt < 4; mt++) {
        float sl = 0.f, ql = 0.f, sh = 0.f, qh = 0.f;
#pragma unroll
        for (int nt = 0; nt < 4; nt++) {
            int c0 = wn + nt * 8 + 2 * (lane & 3);
            float b0 = bias[c0], b1 = bias[c0 + 1];
            float z0 = acc2[mt][nt][0] + b0;
            float z1 = acc2[mt][nt][1] + b1;
            float z2 = acc2[mt][nt][2] + b0;
            float z3 = acc2[mt][nt][3] + b1;
            acc2[mt][nt][0] = z0; acc2[mt][nt][1] = z1;
            acc2[mt][nt][2] = z2; acc2[mt][nt][3] = z3;
            sl += z0 + z1; ql += z0 * z0 + z1 * z1;
            sh += z2 + z3; qh += z2 * z2 + z3 * z3;
        }
        sl += __shfl_xor_sync(0xffffffffu, sl, 1);
        sl += __shfl_xor_sync(0xffffffffu, sl, 2);
        ql += __shfl_xor_sync(0xffffffffu, ql, 1);
        ql += __shfl_xor_sync(0xffffffffu, ql, 2);
        sh += __shfl_xor_sync(0xffffffffu, sh, 1);
        sh += __shfl_xor_sync(0xffffffffu, sh, 2);
        qh += __shfl_xor_sync(0xffffffffu, qh, 1);
        qh += __shfl_xor_sync(0xffffffffu, qh, 2);
        if ((lane & 3) == 0) {
            int rlo = wm + mt * 16 + (lane >> 2);
            spart[rlo * 8 + wni] = sl;
            qpart[rlo * 8 + wni] = ql;
            spart[(rlo + 8) * 8 + wni] = sh;
            qpart[(rlo + 8) * 8 + wni] = qh;
        }
    }
    __syncthreads();
    if (tid < 128) {
        float s = 0.f, q = 0.f;
#pragma unroll
        for (int j = 0; j < 8; j++) { s += spart[tid * 8 + j]; q += qpart[tid * 8 + j]; }
        float mu  = s * (1.0f / HH);
        float var = q * (1.0f / HH) - mu * mu;
        muS[tid] = mu;
        rsS[tid] = rsqrtf(var + LN_EPS);
    }
    __syncthreads();

    __half* tile = (__half*)smem;
    const bool doT = (hTout != nullptr);
    const float* hr = hres + ((size_t)b * NN + bm) * HH;
    float* df       = dstF + ((size_t)b * NN + bm) * HH;

#pragma unroll
    for (int mt = 0; mt < 4; mt++) {
        int rl = wm + mt * 16 + (lane >> 2);
        int rh = rl + 8;
        float mul = muS[rl], rsl = rsS[rl];
        float muh = muS[rh], rsh = rsS[rh];
#pragma unroll
        for (int nt = 0; nt < 4; nt++) {
            int c0 = wn + nt * 8 + 2 * (lane & 3);
            float g0 = gamma[c0], g1 = gamma[c0 + 1];
            float e0 = beta[c0],  e1 = beta[c0 + 1];
            float y0 = fmaxf((acc2[mt][nt][0] - mul) * rsl * g0 + e0, 0.f) + hr[(long)rl * HH + c0];
            float y1 = fmaxf((acc2[mt][nt][1] - mul) * rsl * g1 + e1, 0.f) + hr[(long)rl * HH + c0 + 1];
            float y2 = fmaxf((acc2[mt][nt][2] - muh) * rsh * g0 + e0, 0.f) + hr[(long)rh * HH + c0];
            float y3 = fmaxf((acc2[mt][nt][3] - muh) * rsh * g1 + e1, 0.f) + hr[(long)rh * HH + c0 + 1];
            float2 vlo; vlo.x = y0; vlo.y = y1;
            float2 vhi; vhi.x = y2; vhi.y = y3;
            *(float2*)(df + (long)rl * HH + c0) = vlo;
            *(float2*)(df + (long)rh * HH + c0) = vhi;
            if (doT) {
                tile[(c0)     * 136 + rl] = __float2half_rn(y0);
                tile[(c0 + 1) * 136 + rl] = __float2half_rn(y1);
                tile[(c0)     * 136 + rh] = __float2half_rn(y2);
                tile[(c0 + 1) * 136 + rh] = __float2half_rn(y3);
            }
        }
    }

    if (doT) {
        __syncthreads();
        int c  = tid & 255;
        int hs = tid >> 8;
        __half* dst = hTout + ((size_t)b * HH + c) * NN + bm + hs * 64;
        const uint4* src = (const uint4*)(tile + c * 136 + hs * 64);
#pragma unroll
        for (int g = 0; g < 8; g++)
            ((uint4*)dst)[g] = src[g];
    }
}

// ---------------------------------------------------------------------------
// Launch orchestration (graph-capturable; stream fork for overlap)
// ---------------------------------------------------------------------------
extern "C" void kernel_launch(void* const* d_in, const int* in_sizes, int n_in,
                              void* d_out, int out_size)
{
    const float* node_feat = (const float*)d_in[0];
    const float* edge_w    = (const float*)d_in[1];
    const float* adj       = (const float*)d_in[2];
    const float* W_in      = (const float*)d_in[3];
    const float* b_in      = (const float*)d_in[4];
    const float* g_in      = (const float*)d_in[5];
    const float* bt_in     = (const float*)d_in[6];
    const float* W         = (const float*)d_in[7];
    const float* bvec      = (const float*)d_in[8];
    const float* gamma     = (const float*)d_in[9];
    const float* beta      = (const float*)d_in[10];
    float* out = (float*)d_out;

    __half *na_p, *nf_p, *hTa_p, *hTb_p, *wT_p;
    float *h_p;
    cudaGetSymbolAddress((void**)&na_p,  g_norm_adj);
    cudaGetSymbolAddress((void**)&nf_p,  g_nf);
    cudaGetSymbolAddress((void**)&h_p,   g_h);
    cudaGetSymbolAddress((void**)&hTa_p, g_hTa);
    cudaGetSymbolAddress((void**)&hTb_p, g_hTb);
    cudaGetSymbolAddress((void**)&wT_p,  g_wT);

    cudaFuncSetAttribute(proj_fused,  cudaFuncAttributeMaxDynamicSharedMemorySize, FUSED_SMEM);
    cudaFuncSetAttribute(layer_fused, cudaFuncAttributeMaxDynamicSharedMemorySize, FUSED_SMEM);

    // Lazily created side stream + events (host resources only; no device mem)
    static cudaStream_t s_side = nullptr;
    static cudaEvent_t  s_fork = nullptr, s_join = nullptr;
    static bool s_init = false;
    if (!s_init) {
        s_init = true;
        if (cudaStreamCreateWithFlags(&s_side, cudaStreamNonBlocking) != cudaSuccess)
            s_side = nullptr;
        if (s_side) {
            if (cudaEventCreateWithFlags(&s_fork, cudaEventDisableTiming) != cudaSuccess ||
                cudaEventCreateWithFlags(&s_join, cudaEventDisableTiming) != cudaSuccess) {
                s_side = nullptr;
            }
        }
    }
    const bool fork = (s_side != nullptr);
    cudaStream_t side = fork ? s_side : (cudaStream_t)0;

    const int M_all = BB * NN;
    __half* winT = wT_p;
    __half* wlT  = wT_p + 256 * 512;

    if (fork) {
        cudaEventRecord(s_fork, 0);
        cudaStreamWaitEvent(side, s_fork, 0);
    }

    // main stream: normalized adjacency (memory-bound, ~56us)
    norm_adj_kernel<<<dim3(NN, BB), 256>>>(
        (const float4*)adj, (const float4*)edge_w, na_p);

    // side stream: projection chain (independent of norm_adj)
    transpose_kernel<<<dim3(HH / 32, FF / 32, 1), dim3(32, 8), 0, side>>>(
        W_in, winT, FF, HH, 0, 0);
    transpose_kernel<<<dim3(HH / 32, HH / 32, LL), dim3(32, 8), 0, side>>>(
        W, wlT, HH, HH, (long)HH * HH, (long)HH * HH);
    half_copy_kernel<<<(int)(((long)M_all * FF / 4) / 256), 256, 0, side>>>(
        (const float4*)node_feat, (__half2*)nf_p);
    proj_fused<<<dim3(M_all / 128, 1), 512, FUSED_SMEM, side>>>(
        nf_p, winT, b_in, g_in, bt_in, h_p, hTa_p);

    if (fork) {
        cudaEventRecord(s_join, side);
        cudaStreamWaitEvent((cudaStream_t)0, s_join, 0);
    }

    // fused GNN layers with hT ping-pong (main stream)
    __half* hT_cur = hTa_p;
    __half* hT_nxt = hTb_p;
    for (int l = 0; l < LL; l++) {
        const bool last = (l == LL - 1);
        layer_fused<<<dim3(NN / 128, BB), 512, FUSED_SMEM>>>(
            na_p, hT_cur, wlT + (long)l * HH * HH,
            bvec + (long)l * HH, gamma + (long)l * HH, beta + (long)l * HH,
            h_p,
            last ? out : h_p,
            last ? nullptr : hT_nxt);
        __half* t = hT_cur; hT_cur = hT_nxt; hT_nxt = t;
    }
}